// round 2
// baseline (speedup 1.0000x reference)
#include <cuda_runtime.h>
#include <math.h>
#include <stdint.h>

// Problem constants
#define BB   32
#define NT   20
#define SL   50
#define HLn  50
#define DD   300
#define HH   150
#define G4   600
#define NCOL 1200   // 2 dirs * 600 gates

// ---------------- static device scratch ----------------
__device__ float g_gx[80000 * 1200];          // reused per group (384 MB)
__device__ float g_gxc[640 * 1200];           // conv-LSTM gx
__device__ float g_sentreps[640 * 300];
__device__ float g_histreps[3 * 1600 * 300];
__device__ float g_u[32 * 300];
__device__ float g_WhhT[3 * 2 * 150 * 600];   // A_Whh transposed [m][dir][k][g]
__device__ float g_CWhhT[2 * 150 * 600];
__device__ float g_CWihT[303 * 1200];         // C_Wih transposed [d][c]
__device__ float g_bias2A[3 * 1200];          // bih + bhh (A)
__device__ float g_bias2C[1200];
__device__ int   g_slens[640];
__device__ int   g_hlens[1600];
__device__ int   g_clens[32];

__device__ __forceinline__ float sigf(float x) { return 1.0f / (1.0f + __expf(-x)); }

// ---------------- setup: lengths, transposes, bias folds ----------------
__global__ void setup_kernel(const int* __restrict__ tc, const int* __restrict__ uh,
                             const float* __restrict__ AWhh,
                             const float* __restrict__ Abih, const float* __restrict__ Abhh,
                             const float* __restrict__ CWih, const float* __restrict__ CWhh,
                             const float* __restrict__ Cbih, const float* __restrict__ Cbhh)
{
    int tid  = blockIdx.x * blockDim.x + threadIdx.x;
    int nthr = gridDim.x * blockDim.x;

    // transpose A_Whh: [m*2+dir][600][150] -> [m*2+dir][150][600]
    for (int i = tid; i < 3 * 2 * 600 * 150; i += nthr) {
        int md = i / (600 * 150), r = i % (600 * 150);
        int g = r / 150, kk = r % 150;
        g_WhhT[(md * 150 + kk) * 600 + g] = AWhh[i];
    }
    // transpose C_Whh
    for (int i = tid; i < 2 * 600 * 150; i += nthr) {
        int md = i / (600 * 150), r = i % (600 * 150);
        int g = r / 150, kk = r % 150;
        g_CWhhT[(md * 150 + kk) * 600 + g] = CWhh[i];
    }
    // transpose C_Wih: [c][303] -> [d][c]
    for (int i = tid; i < 1200 * 303; i += nthr) {
        int c = i / 303, d = i % 303;
        g_CWihT[d * 1200 + c] = CWih[i];
    }
    for (int i = tid; i < 3 * 1200; i += nthr) g_bias2A[i] = Abih[i] + Abhh[i];
    for (int i = tid; i < 1200; i += nthr)     g_bias2C[i] = Cbih[i] + Cbhh[i];

    for (int i = tid; i < 640; i += nthr) {
        int c = 0;
        for (int t = 0; t < SL; t++) c += (tc[i * 53 + 3 + t] != 0);
        g_slens[i] = c;
    }
    for (int i = tid; i < 1600; i += nthr) {
        int c = 0;
        for (int t = 0; t < SL; t++) c += (uh[i * 50 + t] != 0);
        g_hlens[i] = c;
    }
    for (int i = tid; i < 32; i += nthr) {
        int c = 0;
        for (int t = 0; t < NT; t++) c += (tc[(i * NT + t) * 53 + 3] != 0);
        g_clens[i] = c;
    }
}

// ---------------- gx GEMM: gather(E) @ Wih^T + (bih+bhh) ----------------
// C[row, c] , row = seq*50 + t, c = dir*600 + g.  BM=BN=128, BK=8, 256 thr, 8x8 micro.
__global__ void gx_gemm(const float* __restrict__ E,
                        const int* __restrict__ tokb, int tstride, int toff,
                        const float* __restrict__ Wih, int m, int R)
{
    __shared__ float As[8][128];
    __shared__ float Bs[8][128];

    int tid  = threadIdx.x;
    int row0 = blockIdx.y * 128;
    int col0 = blockIdx.x * 128;

    int lr = tid >> 1;
    int lk = (tid & 1) * 4;

    int grow = row0 + lr;
    bool aok = (grow < R);
    const float* Arow = E;
    if (aok) {
        int seq = grow / 50, t = grow % 50;
        int tok = tokb[seq * tstride + toff + t];
        Arow = E + (size_t)tok * 300;
    }
    int bcol = col0 + lr;
    bool bok = (bcol < NCOL);
    const float* Brow = bok ? (Wih + (size_t)bcol * 300) : Wih;

    int ty = tid >> 4, tx = tid & 15;
    float acc[8][8];
#pragma unroll
    for (int i = 0; i < 8; i++)
#pragma unroll
        for (int j = 0; j < 8; j++) acc[i][j] = 0.0f;

    for (int k0 = 0; k0 < 300; k0 += 8) {
        float4 av = make_float4(0.f, 0.f, 0.f, 0.f);
        float4 bv = make_float4(0.f, 0.f, 0.f, 0.f);
        bool kin = (k0 + lk) < 300;
        if (aok && kin) av = *reinterpret_cast<const float4*>(Arow + k0 + lk);
        if (bok && kin) bv = *reinterpret_cast<const float4*>(Brow + k0 + lk);
        As[lk + 0][lr] = av.x; As[lk + 1][lr] = av.y; As[lk + 2][lr] = av.z; As[lk + 3][lr] = av.w;
        Bs[lk + 0][lr] = bv.x; Bs[lk + 1][lr] = bv.y; Bs[lk + 2][lr] = bv.z; Bs[lk + 3][lr] = bv.w;
        __syncthreads();

#pragma unroll
        for (int kk = 0; kk < 8; kk++) {
            float4 a0 = *reinterpret_cast<const float4*>(&As[kk][ty * 8]);
            float4 a1 = *reinterpret_cast<const float4*>(&As[kk][ty * 8 + 4]);
            float4 b0 = *reinterpret_cast<const float4*>(&Bs[kk][tx * 8]);
            float4 b1 = *reinterpret_cast<const float4*>(&Bs[kk][tx * 8 + 4]);
            float am[8] = {a0.x, a0.y, a0.z, a0.w, a1.x, a1.y, a1.z, a1.w};
            float bn[8] = {b0.x, b0.y, b0.z, b0.w, b1.x, b1.y, b1.z, b1.w};
#pragma unroll
            for (int i = 0; i < 8; i++)
#pragma unroll
                for (int j = 0; j < 8; j++) acc[i][j] += am[i] * bn[j];
        }
        __syncthreads();
    }

    const float* bias2 = g_bias2A + m * 1200;
#pragma unroll
    for (int i = 0; i < 8; i++) {
        int r = row0 + ty * 8 + i;
        if (r >= R) continue;
        float* orow = g_gx + (size_t)r * NCOL;
#pragma unroll
        for (int jj = 0; jj < 2; jj++) {
            int c = col0 + tx * 8 + jj * 4;
            if (c < NCOL) {
                float4 v;
                v.x = acc[i][jj * 4 + 0] + bias2[c + 0];
                v.y = acc[i][jj * 4 + 1] + bias2[c + 1];
                v.z = acc[i][jj * 4 + 2] + bias2[c + 2];
                v.w = acc[i][jj * 4 + 3] + bias2[c + 3];
                *reinterpret_cast<float4*>(orow + c) = v;
            }
        }
    }
}

// ---------------- conv-LSTM gx: feats[303] @ C_Wih^T + bias ----------------
// 8 rows per block, 256 threads.
__global__ void conv_gx_kernel(const int* __restrict__ tc)
{
    __shared__ float xs[8][304];
    int row0 = blockIdx.x * 8;
    int tid  = threadIdx.x;

    for (int i = tid; i < 8 * 300; i += 256) {
        int rr = i / 300, d = i % 300;
        xs[rr][d] = g_sentreps[(row0 + rr) * 300 + d];
    }
    if (tid < 24) {
        int rr = tid / 3, d = tid % 3;
        xs[rr][300 + d] = (float)tc[(row0 + rr) * 53 + d];
    }
    __syncthreads();

    for (int c = tid; c < NCOL; c += 256) {
        float a0 = g_bias2C[c], a1 = a0, a2 = a0, a3 = a0, a4 = a0, a5 = a0, a6 = a0, a7 = a0;
        a1 = a2 = a3 = a4 = a5 = a6 = a7 = g_bias2C[c];
        for (int d = 0; d < 303; d++) {
            float w = g_CWihT[d * 1200 + c];
            a0 += xs[0][d] * w; a1 += xs[1][d] * w; a2 += xs[2][d] * w; a3 += xs[3][d] * w;
            a4 += xs[4][d] * w; a5 += xs[5][d] * w; a6 += xs[6][d] * w; a7 += xs[7][d] * w;
        }
        g_gxc[(size_t)(row0 + 0) * NCOL + c] = a0;
        g_gxc[(size_t)(row0 + 1) * NCOL + c] = a1;
        g_gxc[(size_t)(row0 + 2) * NCOL + c] = a2;
        g_gxc[(size_t)(row0 + 3) * NCOL + c] = a3;
        g_gxc[(size_t)(row0 + 4) * NCOL + c] = a4;
        g_gxc[(size_t)(row0 + 5) * NCOL + c] = a5;
        g_gxc[(size_t)(row0 + 6) * NCOL + c] = a6;
        g_gxc[(size_t)(row0 + 7) * NCOL + c] = a7;
    }
}

// ---------------- recurrent LSTM (persistent block, 16 units, 160 threads) ----------------
// wsel: 0..2 -> A matrices, 3 -> C.  outsel: 0 target, 1..3 history k-1, 4 conv.
__global__ void __launch_bounds__(160) lstm_recur(int wsel, int outsel, int nSeq, int T)
{
    const float* WhhT = (wsel < 3) ? (g_WhhT + wsel * 2 * 150 * 600) : g_CWhhT;
    const float* gx   = (outsel == 4) ? g_gxc : g_gx;
    const int*   lens = (outsel == 0) ? g_slens : ((outsel == 4) ? g_clens : g_hlens);
    float*     finals = (outsel == 0) ? g_sentreps
                        : ((outsel == 4) ? g_u : (g_histreps + (size_t)(outsel - 1) * 1600 * 300));

    __shared__ float sh_h[16][160];
    __shared__ float sh_G[16][600];
    __shared__ int   sh_len[16], sh_seq[16];

    int tid = threadIdx.x;            // 160
    int u0  = blockIdx.x * 16;
    int dir = (u0 >= nSeq) ? 1 : 0;   // nSeq is a multiple of 16

    if (tid < 16) {
        int ug  = u0 + tid;
        int seq = ug - dir * nSeq;
        sh_seq[tid] = seq;
        sh_len[tid] = lens[seq];
    }
    for (int i = tid; i < 16 * 160; i += 160) ((float*)sh_h)[i] = 0.0f;
    __syncthreads();

    const float* Wb = WhhT + dir * 150 * 600;
    int gA = tid, gB = tid + 160, gC = tid + 320, gD = tid + 480;
    bool vD = (gD < 600);
    int  gDc = vD ? gD : 599;

    int uu = tid / 10;                 // update-phase unit
    int j0 = (tid % 10) * 15;          // update-phase hidden-slot base
    float c_reg[15];
#pragma unroll
    for (int m2 = 0; m2 < 15; m2++) c_reg[m2] = 0.0f;

    for (int s = 0; s < T; s++) {
        float acc0[16], acc1[16], acc2[16], acc3[16];
#pragma unroll
        for (int u = 0; u < 16; u++) { acc0[u] = 0.f; acc1[u] = 0.f; acc2[u] = 0.f; acc3[u] = 0.f; }

#pragma unroll 2
        for (int k = 0; k < 150; k++) {
            const float* wr = Wb + k * 600;
            float w0 = wr[gA], w1 = wr[gB], w2 = wr[gC], w3 = wr[gDc];
#pragma unroll
            for (int u = 0; u < 16; u++) {
                float hv = sh_h[u][k];
                acc0[u] += w0 * hv; acc1[u] += w1 * hv; acc2[u] += w2 * hv; acc3[u] += w3 * hv;
            }
        }

#pragma unroll 1
        for (int u = 0; u < 16; u++) {
            int len = sh_len[u];
            if (s >= len) continue;
            int t = dir ? (len - 1 - s) : s;
            const float* gxr = gx + ((size_t)sh_seq[u] * T + t) * NCOL + dir * 600;
            sh_G[u][gA] = acc0[u] + gxr[gA];
            sh_G[u][gB] = acc1[u] + gxr[gB];
            sh_G[u][gC] = acc2[u] + gxr[gC];
            if (vD) sh_G[u][gD] = acc3[u] + gxr[gD];
        }
        __syncthreads();

        {
            int len = sh_len[uu];
            if (s < len) {
#pragma unroll
                for (int m2 = 0; m2 < 15; m2++) {
                    int j = j0 + m2;
                    float gi = sh_G[uu][j];
                    float gf = sh_G[uu][150 + j];
                    float gg = sh_G[uu][300 + j];
                    float go = sh_G[uu][450 + j];
                    float cc = sigf(gf) * c_reg[m2] + sigf(gi) * tanhf(gg);
                    c_reg[m2] = cc;
                    sh_h[uu][j] = sigf(go) * tanhf(cc);
                }
            }
        }
        __syncthreads();
    }

    {
        int seq = sh_seq[uu];
#pragma unroll
        for (int m2 = 0; m2 < 15; m2++) {
            int j = j0 + m2;
            finals[(size_t)seq * 300 + dir * 150 + j] = sh_h[uu][j];
        }
    }
}

// ---------------- memory hops + output head ----------------
__global__ void hops_kernel(const float* __restrict__ Wout, const float* __restrict__ bout,
                            float* __restrict__ out)
{
    int b = blockIdx.x;
    int tid = threadIdx.x;   // 128
    __shared__ float su[300];
    __shared__ float sc[50];
    __shared__ float wr[4];

    for (int d = tid; d < 300; d += 128) su[d] = g_u[b * 300 + d];
    __syncthreads();

    for (int hop = 0; hop < 2; hop++) {
        const float* rep0 = g_histreps + (size_t)hop * 1600 * 300 + (size_t)b * 50 * 300;
        const float* rep1 = g_histreps + (size_t)(hop + 1) * 1600 * 300 + (size_t)b * 50 * 300;
        int w = tid >> 5, l = tid & 31;
        for (int n = w; n < 50; n += 4) {
            const float* r = rep0 + n * 300;
            float s = 0.0f;
            for (int d = l; d < 300; d += 32) s += r[d] * su[d];
#pragma unroll
            for (int o = 16; o; o >>= 1) s += __shfl_xor_sync(0xffffffffu, s, o);
            if (l == 0) sc[n] = s;
        }
        __syncthreads();
        if (tid < 32) {
            float mx = -1e30f;
            for (int n = tid; n < 50; n += 32) mx = fmaxf(mx, sc[n]);
#pragma unroll
            for (int o = 16; o; o >>= 1) mx = fmaxf(mx, __shfl_xor_sync(0xffffffffu, mx, o));
            float sum = 0.0f;
            for (int n = tid; n < 50; n += 32) { float v = __expf(sc[n] - mx); sc[n] = v; sum += v; }
#pragma unroll
            for (int o = 16; o; o >>= 1) sum += __shfl_xor_sync(0xffffffffu, sum, o);
            float inv = 1.0f / sum;
            for (int n = tid; n < 50; n += 32) sc[n] *= inv;
        }
        __syncthreads();
        for (int d = tid; d < 300; d += 128) {
            float acc = su[d];
            for (int n = 0; n < 50; n++) acc += sc[n] * rep1[n * 300 + d];
            su[d] = acc;
        }
        __syncthreads();
    }

    float s = 0.0f;
    for (int d = tid; d < 300; d += 128) s += su[d] * Wout[d];
#pragma unroll
    for (int o = 16; o; o >>= 1) s += __shfl_xor_sync(0xffffffffu, s, o);
    if ((tid & 31) == 0) wr[tid >> 5] = s;
    __syncthreads();
    if (tid == 0) {
        float t = wr[0] + wr[1] + wr[2] + wr[3];
        out[b] = 1.0f / (1.0f + __expf(-(t + bout[0])));
    }
}

// ---------------- launch ----------------
extern "C" void kernel_launch(void* const* d_in, const int* in_sizes, int n_in,
                              void* d_out, int out_size)
{
    const int*   tc   = (const int*)d_in[0];
    const int*   uh   = (const int*)d_in[1];
    const float* E    = (const float*)d_in[2];
    const float* AWih = (const float*)d_in[3];
    const float* AWhh = (const float*)d_in[4];
    const float* Abih = (const float*)d_in[5];
    const float* Abhh = (const float*)d_in[6];
    const float* CWih = (const float*)d_in[7];
    const float* CWhh = (const float*)d_in[8];
    const float* Cbih = (const float*)d_in[9];
    const float* Cbhh = (const float*)d_in[10];
    const float* Wout = (const float*)d_in[11];
    const float* bout = (const float*)d_in[12];
    float* out = (float*)d_out;

    setup_kernel<<<128, 256>>>(tc, uh, AWhh, Abih, Abhh, CWih, CWhh, Cbih, Cbhh);

    // group 0: target sentences (A[0]); groups 1..3: history with A[0..2]
    for (int grp = 0; grp < 4; grp++) {
        int R    = (grp == 0) ? 32000 : 80000;
        int m    = (grp == 0) ? 0 : (grp - 1);
        const int* tokb = (grp == 0) ? tc : uh;
        int tstride = (grp == 0) ? 53 : 50;
        int toff    = (grp == 0) ? 3 : 0;
        dim3 grid(10, (R + 127) / 128);
        gx_gemm<<<grid, 256>>>(E, tokb, tstride, toff,
                               AWih + (size_t)m * 2 * 600 * 300, m, R);
        int nSeq = (grp == 0) ? 640 : 1600;
        lstm_recur<<<nSeq * 2 / 16, 160>>>(m, grp, nSeq, 50);
    }

    // conversation-level biLSTM
    conv_gx_kernel<<<80, 256>>>(tc);
    lstm_recur<<<4, 160>>>(3, 4, 32, 20);

    // memory hops + head
    hops_kernel<<<32, 128>>>(Wout, bout, out);
    (void)in_sizes; (void)n_in; (void)out_size;
}

// round 4
// speedup vs baseline: 1.0701x; 1.0701x over previous
#include <cuda_runtime.h>
#include <cuda_bf16.h>
#include <math.h>
#include <stdint.h>

// Problem constants
#define BB   32
#define NT   20
#define SL   50
#define DD   300
#define HH   150
#define NCOL 1200   // 2 dirs * 600 gates
#define KP   320    // K padded (10 chunks of 32)
#define NP   1280   // N padded (10 chunks of 128)

// ---------------- static device scratch ----------------
#define GX0_OFF 0ULL
#define GXH_OFF 38400000ULL
#define GXH_SZ  96000000ULL
__device__ float g_gx[326400000];             // 1.31 GB
__device__ float g_gxc[640 * 1200];           // conv-LSTM gx
__device__ float g_sentreps[640 * 300];
__device__ float g_histreps[3 * 1600 * 300];
__device__ float g_u[32 * 300];
__device__ float g_WhhT[3 * 2 * 150 * 600];   // A_Whh transposed [m][dir][k][g]
__device__ float g_CWhhT[2 * 150 * 600];
__device__ float g_CWihT[303 * 1200];         // C_Wih transposed [d][c]
__device__ float g_bias2A[3 * 1200];          // bih + bhh (A)
__device__ float g_bias2C[1200];
__device__ int   g_slens[640];
__device__ int   g_hlens[1600];
__device__ int   g_clens[32];
__device__ __nv_bfloat16 g_Ebf[50000 * KP];   // bf16 E, K-padded (32 MB)
__device__ __nv_bfloat16 g_Wbf[3 * NP * KP];  // bf16 Wih, [n][k] K-contiguous, padded

__device__ __forceinline__ float sigf(float x) { return 1.0f / (1.0f + __expf(-x)); }

__device__ __forceinline__ uint32_t smem_u32(const void* p) {
    uint32_t a;
    asm("{ .reg .u64 t; cvta.to.shared.u64 t, %1; cvt.u32.u64 %0, t; }" : "=r"(a) : "l"(p));
    return a;
}

#define CPA16(dst, src) asm volatile("cp.async.cg.shared.global [%0], [%1], 16;" :: "r"(dst), "l"(src) : "memory")
#define CPA_COMMIT()    asm volatile("cp.async.commit_group;" ::: "memory")
#define CPA_WAIT0()     asm volatile("cp.async.wait_group 0;" ::: "memory")
#define CPA_WAIT1()     asm volatile("cp.async.wait_group 1;" ::: "memory")

#define LDSM_X4(r0, r1, r2, r3, addr) \
    asm volatile("ldmatrix.sync.aligned.m8n8.x4.shared.b16 {%0,%1,%2,%3}, [%4];" \
        : "=r"(r0), "=r"(r1), "=r"(r2), "=r"(r3) : "r"(addr))

#define MMA16816(d, a0, a1, a2, a3, b0, b1) \
    asm volatile("mma.sync.aligned.m16n8k16.row.col.f32.bf16.bf16.f32 " \
        "{%0,%1,%2,%3},{%4,%5,%6,%7},{%8,%9},{%0,%1,%2,%3};" \
        : "+f"((d)[0]), "+f"((d)[1]), "+f"((d)[2]), "+f"((d)[3]) \
        : "r"(a0), "r"(a1), "r"(a2), "r"(a3), "r"(b0), "r"(b1))

// ---------------- setup: lengths, transposes, bias folds, bf16 conversion ----------------
__global__ void setup_kernel(const int* __restrict__ tc, const int* __restrict__ uh,
                             const float* __restrict__ E, const float* __restrict__ AWih,
                             const float* __restrict__ AWhh,
                             const float* __restrict__ Abih, const float* __restrict__ Abhh,
                             const float* __restrict__ CWih, const float* __restrict__ CWhh,
                             const float* __restrict__ Cbih, const float* __restrict__ Cbhh)
{
    int tid  = blockIdx.x * blockDim.x + threadIdx.x;
    int nthr = gridDim.x * blockDim.x;

    for (int i = tid; i < 50000 * KP; i += nthr) {
        int r = i / KP, col = i % KP;
        g_Ebf[i] = __float2bfloat16(col < 300 ? E[(size_t)r * 300 + col] : 0.0f);
    }
    for (int i = tid; i < 3 * NP * KP; i += nthr) {
        int mm = i / (NP * KP), r = (i / KP) % NP, col = i % KP;
        float v = (r < 1200 && col < 300) ? AWih[((size_t)mm * 1200 + r) * 300 + col] : 0.0f;
        g_Wbf[i] = __float2bfloat16(v);
    }
    for (int i = tid; i < 3 * 2 * 600 * 150; i += nthr) {
        int md = i / (600 * 150), r = i % (600 * 150);
        int g = r / 150, kk = r % 150;
        g_WhhT[(md * 150 + kk) * 600 + g] = AWhh[i];
    }
    for (int i = tid; i < 2 * 600 * 150; i += nthr) {
        int md = i / (600 * 150), r = i % (600 * 150);
        int g = r / 150, kk = r % 150;
        g_CWhhT[(md * 150 + kk) * 600 + g] = CWhh[i];
    }
    for (int i = tid; i < 1200 * 303; i += nthr) {
        int c = i / 303, d = i % 303;
        g_CWihT[d * 1200 + c] = CWih[i];
    }
    for (int i = tid; i < 3 * 1200; i += nthr) g_bias2A[i] = Abih[i] + Abhh[i];
    for (int i = tid; i < 1200; i += nthr)     g_bias2C[i] = Cbih[i] + Cbhh[i];

    for (int i = tid; i < 640; i += nthr) {
        int c = 0;
        for (int t = 0; t < SL; t++) c += (tc[i * 53 + 3 + t] != 0);
        g_slens[i] = c;
    }
    for (int i = tid; i < 1600; i += nthr) {
        int c = 0;
        for (int t = 0; t < SL; t++) c += (uh[i * 50 + t] != 0);
        g_hlens[i] = c;
    }
    for (int i = tid; i < 32; i += nthr) {
        int c = 0;
        for (int t = 0; t < NT; t++) c += (tc[(i * NT + t) * 53 + 3] != 0);
        g_clens[i] = c;
    }
}

// ---------------- bf16 warp-MMA gx GEMM: gather(Ebf) @ Wbf^T + bias ----------------
// Block tile 128x128, 8 warps (4 M x 2 N), warp tile 32x64, BK=32, K=320 (10 iters).
// Smem stride 40 bf16 (80B) -> conflict-free ldmatrix.
#define SSTRIDE 40
#define BUFB    (128 * SSTRIDE)   // elements per stage

__global__ void __launch_bounds__(256) gx_mma(const int* __restrict__ tokb, int tstride, int toff,
                                              int m, unsigned long long gxoff)
{
    __shared__ __align__(16) __nv_bfloat16 As[2][BUFB];
    __shared__ __align__(16) __nv_bfloat16 Bs[2][BUFB];

    int tid  = threadIdx.x;
    int lane = tid & 31, wid = tid >> 5;
    int wm = wid & 3, wn = wid >> 2;

    // ---- global load setup (cp.async, 32B per thread per operand per iter) ----
    int lrow = tid >> 1;                        // 0..127
    int cofs = (tid & 1) * 32;                  // byte offset within 64B row-chunk
    int grow = blockIdx.y * 128 + lrow;
    int seq = grow / 50, tt = grow % 50;
    int tok = tokb[seq * tstride + toff + tt];
    const char* asrcb = (const char*)(g_Ebf + (size_t)tok * KP);
    const char* bsrcb = (const char*)(g_Wbf + ((size_t)m * NP + blockIdx.x * 128 + lrow) * KP);
    uint32_t sAs = smem_u32(As), sBs = smem_u32(Bs);
    uint32_t dA0 = sAs + lrow * (SSTRIDE * 2) + cofs;
    uint32_t dB0 = sBs + lrow * (SSTRIDE * 2) + cofs;

    // ---- ldmatrix per-lane address components ----
    int a_row  = wm * 32 + (lane & 15);
    int a_kofs = (lane >> 4) * 8;
    int b_row  = wn * 64 + ((lane >> 4) & 1) * 8 + (lane & 7);
    int b_kofs = ((lane >> 3) & 1) * 8;

    float acc[2][8][4];
#pragma unroll
    for (int i = 0; i < 2; i++)
#pragma unroll
        for (int j = 0; j < 8; j++)
#pragma unroll
            for (int q = 0; q < 4; q++) acc[i][j][q] = 0.0f;

    // prefetch stage 0
    {
        const char* sa = asrcb + cofs;
        const char* sb = bsrcb + cofs;
        CPA16(dA0, sa); CPA16(dA0 + 16, sa + 16);
        CPA16(dB0, sb); CPA16(dB0 + 16, sb + 16);
        CPA_COMMIT();
    }

#pragma unroll 1
    for (int it = 0; it < 10; it++) {
        int buf = it & 1;
        if (it + 1 < 10) {
            int nb = buf ^ 1;
            const char* sa = asrcb + (it + 1) * 64 + cofs;
            const char* sb = bsrcb + (it + 1) * 64 + cofs;
            uint32_t dA = dA0 + nb * (BUFB * 2);
            uint32_t dB = dB0 + nb * (BUFB * 2);
            CPA16(dA, sa); CPA16(dA + 16, sa + 16);
            CPA16(dB, sb); CPA16(dB + 16, sb + 16);
            CPA_COMMIT();
            CPA_WAIT1();
        } else {
            CPA_WAIT0();
        }
        __syncthreads();

        uint32_t abase = sAs + buf * (BUFB * 2);
        uint32_t bbase = sBs + buf * (BUFB * 2);
#pragma unroll
        for (int ks = 0; ks < 2; ks++) {
            uint32_t afr[2][4];
#pragma unroll
            for (int mf = 0; mf < 2; mf++) {
                uint32_t addr = abase + (((a_row + mf * 16) * SSTRIDE) + ks * 16 + a_kofs) * 2;
                LDSM_X4(afr[mf][0], afr[mf][1], afr[mf][2], afr[mf][3], addr);
            }
            uint32_t bfr[4][4];
#pragma unroll
            for (int np = 0; np < 4; np++) {
                uint32_t addr = bbase + (((b_row + np * 16) * SSTRIDE) + ks * 16 + b_kofs) * 2;
                LDSM_X4(bfr[np][0], bfr[np][1], bfr[np][2], bfr[np][3], addr);
            }
#pragma unroll
            for (int mf = 0; mf < 2; mf++)
#pragma unroll
                for (int nf = 0; nf < 8; nf++) {
                    uint32_t b0 = bfr[nf >> 1][(nf & 1) * 2];
                    uint32_t b1 = bfr[nf >> 1][(nf & 1) * 2 + 1];
                    MMA16816(acc[mf][nf], afr[mf][0], afr[mf][1], afr[mf][2], afr[mf][3], b0, b1);
                }
        }
        __syncthreads();
    }

    // ---- epilogue: add bias, store fp32 gx ----
    const float* bias = g_bias2A + m * 1200;
    int orow = blockIdx.y * 128 + wm * 32 + (lane >> 2);
    int ocol0 = blockIdx.x * 128 + wn * 64 + (lane & 3) * 2;
#pragma unroll
    for (int mf = 0; mf < 2; mf++) {
#pragma unroll
        for (int nf = 0; nf < 8; nf++) {
            int col = ocol0 + nf * 8;
            if (col < 1200) {
                float2 bv = *(const float2*)(bias + col);
                float* p0 = g_gx + gxoff + (size_t)(orow + mf * 16) * NCOL + col;
                float2 v0 = make_float2(acc[mf][nf][0] + bv.x, acc[mf][nf][1] + bv.y);
                float2 v1 = make_float2(acc[mf][nf][2] + bv.x, acc[mf][nf][3] + bv.y);
                *(float2*)p0 = v0;
                *(float2*)(p0 + 8 * NCOL) = v1;
            }
        }
    }
}

// ---------------- conv-LSTM gx: feats[303] @ C_Wih^T + bias ----------------
__global__ void conv_gx_kernel(const int* __restrict__ tc)
{
    __shared__ float xs[8][304];
    int row0 = blockIdx.x * 8;
    int tid  = threadIdx.x;

    for (int i = tid; i < 8 * 300; i += 256) {
        int rr = i / 300, d = i % 300;
        xs[rr][d] = g_sentreps[(row0 + rr) * 300 + d];
    }
    if (tid < 24) {
        int rr = tid / 3, d = tid % 3;
        xs[rr][300 + d] = (float)tc[(row0 + rr) * 53 + d];
    }
    __syncthreads();

    for (int c = tid; c < NCOL; c += 256) {
        float a0 = g_bias2C[c], a1 = a0, a2 = a0, a3 = a0, a4 = a0, a5 = a0, a6 = a0, a7 = a0;
        for (int d = 0; d < 303; d++) {
            float w = g_CWihT[d * 1200 + c];
            a0 += xs[0][d] * w; a1 += xs[1][d] * w; a2 += xs[2][d] * w; a3 += xs[3][d] * w;
            a4 += xs[4][d] * w; a5 += xs[5][d] * w; a6 += xs[6][d] * w; a7 += xs[7][d] * w;
        }
        g_gxc[(size_t)(row0 + 0) * NCOL + c] = a0;
        g_gxc[(size_t)(row0 + 1) * NCOL + c] = a1;
        g_gxc[(size_t)(row0 + 2) * NCOL + c] = a2;
        g_gxc[(size_t)(row0 + 3) * NCOL + c] = a3;
        g_gxc[(size_t)(row0 + 4) * NCOL + c] = a4;
        g_gxc[(size_t)(row0 + 5) * NCOL + c] = a5;
        g_gxc[(size_t)(row0 + 6) * NCOL + c] = a6;
        g_gxc[(size_t)(row0 + 7) * NCOL + c] = a7;
    }
}

// ---------------- recurrent LSTM (persistent block, 16 units, 160 threads) ----------------
__global__ void __launch_bounds__(160) lstm_recur_all(int conv)
{
    const float* WhhT; const float* gx; const int* lens; float* finals;
    int nSeq, T, blk;
    if (conv) {
        WhhT = g_CWhhT; gx = g_gxc; lens = g_clens; finals = g_u;
        nSeq = 32; T = 20; blk = blockIdx.x;
    } else {
        int b = blockIdx.x;
        T = 50;
        if (b < 80) {
            blk = b; nSeq = 640; WhhT = g_WhhT; gx = g_gx;
            lens = g_slens; finals = g_sentreps;
        } else {
            int g = (b - 80) / 200;
            blk = (b - 80) % 200; nSeq = 1600;
            WhhT = g_WhhT + (size_t)g * 2 * 150 * 600;
            gx = g_gx + GXH_OFF + (size_t)g * GXH_SZ;
            lens = g_hlens;
            finals = g_histreps + (size_t)g * 480000;
        }
    }

    __shared__ float sh_h[16][160];
    __shared__ float sh_G[16][600];
    __shared__ int   sh_len[16], sh_seq[16];

    int tid = threadIdx.x;            // 160
    int u0  = blk * 16;
    int dir = (u0 >= nSeq) ? 1 : 0;   // nSeq is a multiple of 16

    if (tid < 16) {
        int ug  = u0 + tid;
        int seq = ug - dir * nSeq;
        sh_seq[tid] = seq;
        sh_len[tid] = lens[seq];
    }
    for (int i = tid; i < 16 * 160; i += 160) ((float*)sh_h)[i] = 0.0f;
    __syncthreads();

    const float* Wb = WhhT + dir * 150 * 600;
    int gA = tid, gB = tid + 160, gC = tid + 320, gD = tid + 480;
    bool vD = (gD < 600);
    int  gDc = vD ? gD : 599;

    int uu = tid / 10;
    int j0 = (tid % 10) * 15;
    float c_reg[15];
#pragma unroll
    for (int m2 = 0; m2 < 15; m2++) c_reg[m2] = 0.0f;

    for (int s = 0; s < T; s++) {
        float acc0[16], acc1[16], acc2[16], acc3[16];
#pragma unroll
        for (int u = 0; u < 16; u++) { acc0[u] = 0.f; acc1[u] = 0.f; acc2[u] = 0.f; acc3[u] = 0.f; }

#pragma unroll 2
        for (int k = 0; k < 150; k++) {
            const float* wr = Wb + k * 600;
            float w0 = wr[gA], w1 = wr[gB], w2 = wr[gC], w3 = wr[gDc];
#pragma unroll
            for (int u = 0; u < 16; u++) {
                float hv = sh_h[u][k];
                acc0[u] += w0 * hv; acc1[u] += w1 * hv; acc2[u] += w2 * hv; acc3[u] += w3 * hv;
            }
        }

#pragma unroll 1
        for (int u = 0; u < 16; u++) {
            int len = sh_len[u];
            if (s >= len) continue;
            int t = dir ? (len - 1 - s) : s;
            const float* gxr = gx + ((size_t)sh_seq[u] * T + t) * NCOL + dir * 600;
            sh_G[u][gA] = acc0[u] + gxr[gA];
            sh_G[u][gB] = acc1[u] + gxr[gB];
            sh_G[u][gC] = acc2[u] + gxr[gC];
            if (vD) sh_G[u][gD] = acc3[u] + gxr[gD];
        }
        __syncthreads();

        {
            int len = sh_len[uu];
            if (s < len) {
#pragma unroll
                for (int m2 = 0; m2 < 15; m2++) {
                    int j = j0 + m2;
                    float gi = sh_G[uu][j];
                    float gf = sh_G[uu][150 + j];
                    float gg = sh_G[uu][300 + j];
                    float go = sh_G[uu][450 + j];
                    float cc = sigf(gf) * c_reg[m2] + sigf(gi) * tanhf(gg);
                    c_reg[m2] = cc;
                    sh_h[uu][j] = sigf(go) * tanhf(cc);
                }
            }
        }
        __syncthreads();
    }

    {
        int seq = sh_seq[uu];
#pragma unroll
        for (int m2 = 0; m2 < 15; m2++) {
            int j = j0 + m2;
            finals[(size_t)seq * 300 + dir * 150 + j] = sh_h[uu][j];
        }
    }
}

// ---------------- memory hops + output head ----------------
__global__ void hops_kernel(const float* __restrict__ Wout, const float* __restrict__ bout,
                            float* __restrict__ out)
{
    int b = blockIdx.x;
    int tid = threadIdx.x;   // 128
    __shared__ float su[300];
    __shared__ float sc[50];
    __shared__ float wr[4];

    for (int d = tid; d < 300; d += 128) su[d] = g_u[b * 300 + d];
    __syncthreads();

    for (int hop = 0; hop < 2; hop++) {
        const float* rep0 = g_histreps + (size_t)hop * 1600 * 300 + (size_t)b * 50 * 300;
        const float* rep1 = g_histreps + (size_t)(hop + 1) * 1600 * 300 + (size_t)b * 50 * 300;
        int w = tid >> 5, l = tid & 31;
        for (int n = w; n < 50; n += 4) {
            const float* r = rep0 + n * 300;
            float s = 0.0f;
            for (int d = l; d < 300; d += 32) s += r[d] * su[d];
#pragma unroll
            for (int o = 16; o; o >>= 1) s += __shfl_xor_sync(0xffffffffu, s, o);
            if (l == 0) sc[n] = s;
        }
        __syncthreads();
        if (tid < 32) {
            float mx = -1e30f;
            for (int n = tid; n < 50; n += 32) mx = fmaxf(mx, sc[n]);
#pragma unroll
            for (int o = 16; o; o >>= 1) mx = fmaxf(mx, __shfl_xor_sync(0xffffffffu, mx, o));
            float sum = 0.0f;
            for (int n = tid; n < 50; n += 32) { float v = __expf(sc[n] - mx); sc[n] = v; sum += v; }
#pragma unroll
            for (int o = 16; o; o >>= 1) sum += __shfl_xor_sync(0xffffffffu, sum, o);
            float inv = 1.0f / sum;
            for (int n = tid; n < 50; n += 32) sc[n] *= inv;
        }
        __syncthreads();
        for (int d = tid; d < 300; d += 128) {
            float acc = su[d];
            for (int n = 0; n < 50; n++) acc += sc[n] * rep1[n * 300 + d];
            su[d] = acc;
        }
        __syncthreads();
    }

    float s = 0.0f;
    for (int d = tid; d < 300; d += 128) s += su[d] * Wout[d];
#pragma unroll
    for (int o = 16; o; o >>= 1) s += __shfl_xor_sync(0xffffffffu, s, o);
    if ((tid & 31) == 0) wr[tid >> 5] = s;
    __syncthreads();
    if (tid == 0) {
        float t = wr[0] + wr[1] + wr[2] + wr[3];
        out[b] = 1.0f / (1.0f + __expf(-(t + bout[0])));
    }
}

// ---------------- launch ----------------
extern "C" void kernel_launch(void* const* d_in, const int* in_sizes, int n_in,
                              void* d_out, int out_size)
{
    const int*   tc   = (const int*)d_in[0];
    const int*   uh   = (const int*)d_in[1];
    const float* E    = (const float*)d_in[2];
    const float* AWih = (const float*)d_in[3];
    const float* AWhh = (const float*)d_in[4];
    const float* Abih = (const float*)d_in[5];
    const float* Abhh = (const float*)d_in[6];
    const float* CWih = (const float*)d_in[7];
    const float* CWhh = (const float*)d_in[8];
    const float* Cbih = (const float*)d_in[9];
    const float* Cbhh = (const float*)d_in[10];
    const float* Wout = (const float*)d_in[11];
    const float* bout = (const float*)d_in[12];
    float* out = (float*)d_out;

    setup_kernel<<<264, 256>>>(tc, uh, E, AWih, AWhh, Abih, Abhh, CWih, CWhh, Cbih, Cbhh);

    // group 0: target sentences (A[0]); groups 1..3: history with A[0..2]
    gx_mma<<<dim3(10, 250), 256>>>(tc, 53, 3, 0, GX0_OFF);
    for (int g = 0; g < 3; g++)
        gx_mma<<<dim3(10, 625), 256>>>(uh, 50, 0, g, GXH_OFF + (unsigned long long)g * GXH_SZ);

    // all big recurrences in one launch (80 + 3*200 blocks)
    lstm_recur_all<<<680, 160>>>(0);

    // conversation-level biLSTM
    conv_gx_kernel<<<80, 256>>>(tc);
    lstm_recur_all<<<4, 160>>>(1);

    // memory hops + head
    hops_kernel<<<32, 128>>>(Wout, bout, out);
    (void)in_sizes; (void)n_in; (void)out_size;
}

// round 5
// speedup vs baseline: 1.9747x; 1.8453x over previous
#include <cuda_runtime.h>
#include <cuda_bf16.h>
#include <math.h>
#include <stdint.h>

// Problem constants
#define BB   32
#define NT   20
#define SL   50
#define DD   300
#define HH   150
#define NCOL 1200   // 2 dirs * 600 gates
#define KP   320    // K padded (10 chunks of 32)
#define NP   1280   // N padded (10 chunks of 128)

// ---------------- static device scratch ----------------
#define GX0_OFF 0ULL
#define GXH_OFF 38400000ULL
#define GXH_SZ  96000000ULL
__device__ float g_gx[326400000];             // 1.31 GB
__device__ float g_gxc[640 * 1200];           // conv-LSTM gx
__device__ float g_sentreps[640 * 300];
__device__ float g_histreps[3 * 1600 * 300];
__device__ float g_u[32 * 300];
__device__ float g_WhhT[3 * 2 * 150 * 600];   // A_Whh transposed [m][dir][k][g]
__device__ float g_CWhhT[2 * 150 * 600];
__device__ float g_CWihT[303 * 1200];         // C_Wih transposed [d][c]
__device__ float g_bias2A[3 * 1200];          // bih + bhh (A)
__device__ float g_bias2C[1200];
__device__ int   g_slens[640];
__device__ int   g_hlens[1600];
__device__ int   g_clens[32];
__device__ __nv_bfloat16 g_Ebf[50000 * KP];   // bf16 E, K-padded (32 MB)
__device__ __nv_bfloat16 g_Wbf[3 * NP * KP];  // bf16 Wih, [n][k] K-contiguous, padded

__device__ __forceinline__ float sigf(float x) { return 1.0f / (1.0f + __expf(-x)); }

__device__ __forceinline__ uint32_t smem_u32(const void* p) {
    uint32_t a;
    asm("{ .reg .u64 t; cvta.to.shared.u64 t, %1; cvt.u32.u64 %0, t; }" : "=r"(a) : "l"(p));
    return a;
}

#define CPA16(dst, src) asm volatile("cp.async.cg.shared.global [%0], [%1], 16;" :: "r"(dst), "l"(src) : "memory")
#define CPA_COMMIT()    asm volatile("cp.async.commit_group;" ::: "memory")
#define CPA_WAIT0()     asm volatile("cp.async.wait_group 0;" ::: "memory")
#define CPA_WAIT1()     asm volatile("cp.async.wait_group 1;" ::: "memory")
#define CPA_WAIT2()     asm volatile("cp.async.wait_group 2;" ::: "memory")

#define LDSM_X4(r0, r1, r2, r3, addr) \
    asm volatile("ldmatrix.sync.aligned.m8n8.x4.shared.b16 {%0,%1,%2,%3}, [%4];" \
        : "=r"(r0), "=r"(r1), "=r"(r2), "=r"(r3) : "r"(addr))

#define MMA16816(d, a0, a1, a2, a3, b0, b1) \
    asm volatile("mma.sync.aligned.m16n8k16.row.col.f32.bf16.bf16.f32 " \
        "{%0,%1,%2,%3},{%4,%5,%6,%7},{%8,%9},{%0,%1,%2,%3};" \
        : "+f"((d)[0]), "+f"((d)[1]), "+f"((d)[2]), "+f"((d)[3]) \
        : "r"(a0), "r"(a1), "r"(a2), "r"(a3), "r"(b0), "r"(b1))

// ---------------- setup: lengths, transposes, bias folds, bf16 conversion ----------------
__global__ void setup_kernel(const int* __restrict__ tc, const int* __restrict__ uh,
                             const float* __restrict__ E, const float* __restrict__ AWih,
                             const float* __restrict__ AWhh,
                             const float* __restrict__ Abih, const float* __restrict__ Abhh,
                             const float* __restrict__ CWih, const float* __restrict__ CWhh,
                             const float* __restrict__ Cbih, const float* __restrict__ Cbhh)
{
    int tid  = blockIdx.x * blockDim.x + threadIdx.x;
    int nthr = gridDim.x * blockDim.x;

    for (int i = tid; i < 50000 * KP; i += nthr) {
        int r = i / KP, col = i % KP;
        g_Ebf[i] = __float2bfloat16(col < 300 ? E[(size_t)r * 300 + col] : 0.0f);
    }
    for (int i = tid; i < 3 * NP * KP; i += nthr) {
        int mm = i / (NP * KP), r = (i / KP) % NP, col = i % KP;
        float v = (r < 1200 && col < 300) ? AWih[((size_t)mm * 1200 + r) * 300 + col] : 0.0f;
        g_Wbf[i] = __float2bfloat16(v);
    }
    for (int i = tid; i < 3 * 2 * 600 * 150; i += nthr) {
        int md = i / (600 * 150), r = i % (600 * 150);
        int g = r / 150, kk = r % 150;
        g_WhhT[(md * 150 + kk) * 600 + g] = AWhh[i];
    }
    for (int i = tid; i < 2 * 600 * 150; i += nthr) {
        int md = i / (600 * 150), r = i % (600 * 150);
        int g = r / 150, kk = r % 150;
        g_CWhhT[(md * 150 + kk) * 600 + g] = CWhh[i];
    }
    for (int i = tid; i < 1200 * 303; i += nthr) {
        int c = i / 303, d = i % 303;
        g_CWihT[d * 1200 + c] = CWih[i];
    }
    for (int i = tid; i < 3 * 1200; i += nthr) g_bias2A[i] = Abih[i] + Abhh[i];
    for (int i = tid; i < 1200; i += nthr)     g_bias2C[i] = Cbih[i] + Cbhh[i];

    for (int i = tid; i < 640; i += nthr) {
        int c = 0;
        for (int t = 0; t < SL; t++) c += (tc[i * 53 + 3 + t] != 0);
        g_slens[i] = c;
    }
    for (int i = tid; i < 1600; i += nthr) {
        int c = 0;
        for (int t = 0; t < SL; t++) c += (uh[i * 50 + t] != 0);
        g_hlens[i] = c;
    }
    for (int i = tid; i < 32; i += nthr) {
        int c = 0;
        for (int t = 0; t < NT; t++) c += (tc[(i * NT + t) * 53 + 3] != 0);
        g_clens[i] = c;
    }
}

// ---------------- bf16 warp-MMA gx GEMM, A-resident multi-matrix version ----------------
// One CTA: 128 rows (A gathered ONCE into smem, 100 KB) x [nmats x 1200] cols.
// Flattened iteration space: it = mat*100 + nc*10 + k  (BK=32, 10 k-iters, 10 n-chunks).
// B: 4-stage cp.async pipeline (8 KB/stage) from L2-resident weights.
#define SSTRIDE 40               // bf16 elements per row in smem (80 B)
#define ACH 10240                // bytes per A K-chunk (128 rows * 80 B)
#define BST 10240                // bytes per B stage
#define SM_B_OFF (10 * ACH)      // 102400
#define GSM_BYTES (10 * ACH + 4 * BST)   // 143360

__global__ void __launch_bounds__(256) gx_mma(const int* __restrict__ tokb, int tstride, int toff,
                                              int nmats, unsigned long long gxbase,
                                              unsigned long long gxstride)
{
    extern __shared__ char smem[];
    uint32_t sA = smem_u32(smem);
    uint32_t sB = sA + SM_B_OFF;

    int tid  = threadIdx.x;
    int lane = tid & 31, wid = tid >> 5;
    int wm = wid & 3, wn = wid >> 2;

    // ---- A gather (once): 128 rows x 320 bf16, chunked [k-chunk][row][32 bf16 + pad] ----
    int lrow = tid >> 1, hf = tid & 1;
    int grow = blockIdx.x * 128 + lrow;
    int seq = grow / 50, tt = grow % 50;
    int tok = tokb[seq * tstride + toff + tt];
    const char* asrc = (const char*)(g_Ebf + (size_t)tok * KP);
#pragma unroll
    for (int ci = 0; ci < 5; ci++) {
        int c = ci * 2 + hf;
        uint32_t dst = sA + c * ACH + lrow * 80;
        const char* src = asrc + c * 64;
        CPA16(dst, src); CPA16(dst + 16, src + 16);
        CPA16(dst + 32, src + 32); CPA16(dst + 48, src + 48);
    }
    CPA_COMMIT();   // group: A

    int cofs = hf * 32;
    uint32_t dB0 = sB + lrow * 80 + cofs;
    int total = nmats * 100;

    // ---- prologue: B stages 0..2 (it = 0,1,2 -> mat 0, nc 0, k = it) ----
#pragma unroll
    for (int it = 0; it < 3; it++) {
        const char* src = (const char*)(g_Wbf + (size_t)lrow * KP + it * 32) + cofs;
        uint32_t dst = dB0 + it * BST;
        CPA16(dst, src); CPA16(dst + 16, src + 16);
        CPA_COMMIT();
    }

    // ---- ldmatrix per-lane address components ----
    int a_row  = wm * 32 + (lane & 15);
    int a_kofs = (lane >> 4) * 8;
    int b_row  = wn * 64 + ((lane >> 4) & 1) * 8 + (lane & 7);
    int b_kofs = ((lane >> 3) & 1) * 8;

    float acc[2][8][4];

#pragma unroll 1
    for (int it = 0; it < total; it++) {
        int k = it % 10;

        // wait for stage `it` (n = min(2, total-1-it) handles the tail)
        int rem = total - 1 - it;
        if (rem >= 2)      CPA_WAIT2();
        else if (rem == 1) CPA_WAIT1();
        else               CPA_WAIT0();
        __syncthreads();

        // prefetch stage it+3 (buffer reuse protected by the barrier above)
        int itp = it + 3;
        if (itp < total) {
            int matp = itp / 100, ncp = (itp / 10) % 10, kp = itp % 10;
            const char* src = (const char*)(g_Wbf +
                ((size_t)matp * NP + ncp * 128 + lrow) * KP + kp * 32) + cofs;
            uint32_t dst = dB0 + (itp & 3) * BST;
            CPA16(dst, src); CPA16(dst + 16, src + 16);
            CPA_COMMIT();
        }

        if (k == 0) {
#pragma unroll
            for (int i = 0; i < 2; i++)
#pragma unroll
                for (int j = 0; j < 8; j++)
#pragma unroll
                    for (int q = 0; q < 4; q++) acc[i][j][q] = 0.0f;
        }

        uint32_t abase = sA + k * ACH;
        uint32_t bbase = sB + (it & 3) * BST;
#pragma unroll
        for (int ks = 0; ks < 2; ks++) {
            uint32_t afr[2][4];
#pragma unroll
            for (int mf = 0; mf < 2; mf++) {
                uint32_t addr = abase + (((a_row + mf * 16) * SSTRIDE) + ks * 16 + a_kofs) * 2;
                LDSM_X4(afr[mf][0], afr[mf][1], afr[mf][2], afr[mf][3], addr);
            }
            uint32_t bfr[4][4];
#pragma unroll
            for (int np = 0; np < 4; np++) {
                uint32_t addr = bbase + (((b_row + np * 16) * SSTRIDE) + ks * 16 + b_kofs) * 2;
                LDSM_X4(bfr[np][0], bfr[np][1], bfr[np][2], bfr[np][3], addr);
            }
#pragma unroll
            for (int mf = 0; mf < 2; mf++)
#pragma unroll
                for (int nf = 0; nf < 8; nf++) {
                    uint32_t b0 = bfr[nf >> 1][(nf & 1) * 2];
                    uint32_t b1 = bfr[nf >> 1][(nf & 1) * 2 + 1];
                    MMA16816(acc[mf][nf], afr[mf][0], afr[mf][1], afr[mf][2], afr[mf][3], b0, b1);
                }
        }

        if (k == 9) {
            // ---- epilogue for this (mat, nc): add bias, store fp32 gx ----
            int mat = it / 100, ncl = (it / 10) % 10;
            const float* bias = g_bias2A + mat * 1200;
            float* gxp = g_gx + gxbase + (size_t)mat * gxstride;
            int orow  = blockIdx.x * 128 + wm * 32 + (lane >> 2);
            int ocol0 = ncl * 128 + wn * 64 + (lane & 3) * 2;
#pragma unroll
            for (int mf = 0; mf < 2; mf++) {
#pragma unroll
                for (int nf = 0; nf < 8; nf++) {
                    int col = ocol0 + nf * 8;
                    if (col < 1200) {
                        float2 bv = *(const float2*)(bias + col);
                        float* p0 = gxp + (size_t)(orow + mf * 16) * NCOL + col;
                        *(float2*)p0 = make_float2(acc[mf][nf][0] + bv.x, acc[mf][nf][1] + bv.y);
                        *(float2*)(p0 + 8 * NCOL) =
                            make_float2(acc[mf][nf][2] + bv.x, acc[mf][nf][3] + bv.y);
                    }
                }
            }
        }
    }
}

// ---------------- conv-LSTM gx: feats[303] @ C_Wih^T + bias ----------------
__global__ void conv_gx_kernel(const int* __restrict__ tc)
{
    __shared__ float xs[8][304];
    int row0 = blockIdx.x * 8;
    int tid  = threadIdx.x;

    for (int i = tid; i < 8 * 300; i += 256) {
        int rr = i / 300, d = i % 300;
        xs[rr][d] = g_sentreps[(row0 + rr) * 300 + d];
    }
    if (tid < 24) {
        int rr = tid / 3, d = tid % 3;
        xs[rr][300 + d] = (float)tc[(row0 + rr) * 53 + d];
    }
    __syncthreads();

    for (int c = tid; c < NCOL; c += 256) {
        float a0 = g_bias2C[c], a1 = a0, a2 = a0, a3 = a0, a4 = a0, a5 = a0, a6 = a0, a7 = a0;
        for (int d = 0; d < 303; d++) {
            float w = g_CWihT[d * 1200 + c];
            a0 += xs[0][d] * w; a1 += xs[1][d] * w; a2 += xs[2][d] * w; a3 += xs[3][d] * w;
            a4 += xs[4][d] * w; a5 += xs[5][d] * w; a6 += xs[6][d] * w; a7 += xs[7][d] * w;
        }
        g_gxc[(size_t)(row0 + 0) * NCOL + c] = a0;
        g_gxc[(size_t)(row0 + 1) * NCOL + c] = a1;
        g_gxc[(size_t)(row0 + 2) * NCOL + c] = a2;
        g_gxc[(size_t)(row0 + 3) * NCOL + c] = a3;
        g_gxc[(size_t)(row0 + 4) * NCOL + c] = a4;
        g_gxc[(size_t)(row0 + 5) * NCOL + c] = a5;
        g_gxc[(size_t)(row0 + 6) * NCOL + c] = a6;
        g_gxc[(size_t)(row0 + 7) * NCOL + c] = a7;
    }
}

// ---------------- recurrent LSTM (persistent block, 16 units, 160 threads) ----------------
__global__ void __launch_bounds__(160) lstm_recur_all(int conv)
{
    const float* WhhT; const float* gx; const int* lens; float* finals;
    int nSeq, T, blk;
    if (conv) {
        WhhT = g_CWhhT; gx = g_gxc; lens = g_clens; finals = g_u;
        nSeq = 32; T = 20; blk = blockIdx.x;
    } else {
        int b = blockIdx.x;
        T = 50;
        if (b < 80) {
            blk = b; nSeq = 640; WhhT = g_WhhT; gx = g_gx;
            lens = g_slens; finals = g_sentreps;
        } else {
            int g = (b - 80) / 200;
            blk = (b - 80) % 200; nSeq = 1600;
            WhhT = g_WhhT + (size_t)g * 2 * 150 * 600;
            gx = g_gx + GXH_OFF + (size_t)g * GXH_SZ;
            lens = g_hlens;
            finals = g_histreps + (size_t)g * 480000;
        }
    }

    __shared__ float sh_h[16][160];
    __shared__ float sh_G[16][600];
    __shared__ int   sh_len[16], sh_seq[16];

    int tid = threadIdx.x;            // 160
    int u0  = blk * 16;
    int dir = (u0 >= nSeq) ? 1 : 0;   // nSeq is a multiple of 16

    if (tid < 16) {
        int ug  = u0 + tid;
        int seq = ug - dir * nSeq;
        sh_seq[tid] = seq;
        sh_len[tid] = lens[seq];
    }
    for (int i = tid; i < 16 * 160; i += 160) ((float*)sh_h)[i] = 0.0f;
    __syncthreads();

    const float* Wb = WhhT + dir * 150 * 600;
    int gA = tid, gB = tid + 160, gC = tid + 320, gD = tid + 480;
    bool vD = (gD < 600);
    int  gDc = vD ? gD : 599;

    int uu = tid / 10;
    int j0 = (tid % 10) * 15;
    float c_reg[15];
#pragma unroll
    for (int m2 = 0; m2 < 15; m2++) c_reg[m2] = 0.0f;

    for (int s = 0; s < T; s++) {
        float acc0[16], acc1[16], acc2[16], acc3[16];
#pragma unroll
        for (int u = 0; u < 16; u++) { acc0[u] = 0.f; acc1[u] = 0.f; acc2[u] = 0.f; acc3[u] = 0.f; }

#pragma unroll 2
        for (int k = 0; k < 150; k++) {
            const float* wr = Wb + k * 600;
            float w0 = wr[gA], w1 = wr[gB], w2 = wr[gC], w3 = wr[gDc];
#pragma unroll
            for (int u = 0; u < 16; u++) {
                float hv = sh_h[u][k];
                acc0[u] += w0 * hv; acc1[u] += w1 * hv; acc2[u] += w2 * hv; acc3[u] += w3 * hv;
            }
        }

#pragma unroll 1
        for (int u = 0; u < 16; u++) {
            int len = sh_len[u];
            if (s >= len) continue;
            int t = dir ? (len - 1 - s) : s;
            const float* gxr = gx + ((size_t)sh_seq[u] * T + t) * NCOL + dir * 600;
            sh_G[u][gA] = acc0[u] + gxr[gA];
            sh_G[u][gB] = acc1[u] + gxr[gB];
            sh_G[u][gC] = acc2[u] + gxr[gC];
            if (vD) sh_G[u][gD] = acc3[u] + gxr[gD];
        }
        __syncthreads();

        {
            int len = sh_len[uu];
            if (s < len) {
#pragma unroll
                for (int m2 = 0; m2 < 15; m2++) {
                    int j = j0 + m2;
                    float gi = sh_G[uu][j];
                    float gf = sh_G[uu][150 + j];
                    float gg = sh_G[uu][300 + j];
                    float go = sh_G[uu][450 + j];
                    float cc = sigf(gf) * c_reg[m2] + sigf(gi) * tanhf(gg);
                    c_reg[m2] = cc;
                    sh_h[uu][j] = sigf(go) * tanhf(cc);
                }
            }
        }
        __syncthreads();
    }

    {
        int seq = sh_seq[uu];
#pragma unroll
        for (int m2 = 0; m2 < 15; m2++) {
            int j = j0 + m2;
            finals[(size_t)seq * 300 + dir * 150 + j] = sh_h[uu][j];
        }
    }
}

// ---------------- memory hops + output head ----------------
__global__ void hops_kernel(const float* __restrict__ Wout, const float* __restrict__ bout,
                            float* __restrict__ out)
{
    int b = blockIdx.x;
    int tid = threadIdx.x;   // 128
    __shared__ float su[300];
    __shared__ float sc[50];
    __shared__ float wr[4];

    for (int d = tid; d < 300; d += 128) su[d] = g_u[b * 300 + d];
    __syncthreads();

    for (int hop = 0; hop < 2; hop++) {
        const float* rep0 = g_histreps + (size_t)hop * 1600 * 300 + (size_t)b * 50 * 300;
        const float* rep1 = g_histreps + (size_t)(hop + 1) * 1600 * 300 + (size_t)b * 50 * 300;
        int w = tid >> 5, l = tid & 31;
        for (int n = w; n < 50; n += 4) {
            const float* r = rep0 + n * 300;
            float s = 0.0f;
            for (int d = l; d < 300; d += 32) s += r[d] * su[d];
#pragma unroll
            for (int o = 16; o; o >>= 1) s += __shfl_xor_sync(0xffffffffu, s, o);
            if (l == 0) sc[n] = s;
        }
        __syncthreads();
        if (tid < 32) {
            float mx = -1e30f;
            for (int n = tid; n < 50; n += 32) mx = fmaxf(mx, sc[n]);
#pragma unroll
            for (int o = 16; o; o >>= 1) mx = fmaxf(mx, __shfl_xor_sync(0xffffffffu, mx, o));
            float sum = 0.0f;
            for (int n = tid; n < 50; n += 32) { float v = __expf(sc[n] - mx); sc[n] = v; sum += v; }
#pragma unroll
            for (int o = 16; o; o >>= 1) sum += __shfl_xor_sync(0xffffffffu, sum, o);
            float inv = 1.0f / sum;
            for (int n = tid; n < 50; n += 32) sc[n] *= inv;
        }
        __syncthreads();
        for (int d = tid; d < 300; d += 128) {
            float acc = su[d];
            for (int n = 0; n < 50; n++) acc += sc[n] * rep1[n * 300 + d];
            su[d] = acc;
        }
        __syncthreads();
    }

    float s = 0.0f;
    for (int d = tid; d < 300; d += 128) s += su[d] * Wout[d];
#pragma unroll
    for (int o = 16; o; o >>= 1) s += __shfl_xor_sync(0xffffffffu, s, o);
    if ((tid & 31) == 0) wr[tid >> 5] = s;
    __syncthreads();
    if (tid == 0) {
        float t = wr[0] + wr[1] + wr[2] + wr[3];
        out[b] = 1.0f / (1.0f + __expf(-(t + bout[0])));
    }
}

// ---------------- launch ----------------
extern "C" void kernel_launch(void* const* d_in, const int* in_sizes, int n_in,
                              void* d_out, int out_size)
{
    const int*   tc   = (const int*)d_in[0];
    const int*   uh   = (const int*)d_in[1];
    const float* E    = (const float*)d_in[2];
    const float* AWih = (const float*)d_in[3];
    const float* AWhh = (const float*)d_in[4];
    const float* Abih = (const float*)d_in[5];
    const float* Abhh = (const float*)d_in[6];
    const float* CWih = (const float*)d_in[7];
    const float* CWhh = (const float*)d_in[8];
    const float* Cbih = (const float*)d_in[9];
    const float* Cbhh = (const float*)d_in[10];
    const float* Wout = (const float*)d_in[11];
    const float* bout = (const float*)d_in[12];
    float* out = (float*)d_out;

    cudaFuncSetAttribute(gx_mma, cudaFuncAttributeMaxDynamicSharedMemorySize, GSM_BYTES);

    setup_kernel<<<264, 256>>>(tc, uh, E, AWih, AWhh, Abih, Abhh, CWih, CWhh, Cbih, Cbhh);

    // target sentences: A[0] only; history: all 3 matrices per A-tile
    gx_mma<<<250, 256, GSM_BYTES>>>(tc, 53, 3, 1, GX0_OFF, 0ULL);
    gx_mma<<<625, 256, GSM_BYTES>>>(uh, 50, 0, 3, GXH_OFF, GXH_SZ);

    // all big recurrences in one launch (80 + 3*200 blocks)
    lstm_recur_all<<<680, 160>>>(0);

    // conversation-level biLSTM
    conv_gx_kernel<<<80, 256>>>(tc);
    lstm_recur_all<<<4, 160>>>(1);

    // memory hops + head
    hops_kernel<<<32, 128>>>(Wout, bout, out);
    (void)in_sizes; (void)n_in; (void)out_size;
}

// round 7
// speedup vs baseline: 3.2982x; 1.6702x over previous
#include <cuda_runtime.h>
#include <cuda_bf16.h>
#include <math.h>
#include <stdint.h>

// Problem constants
#define BB   32
#define NT   20
#define SL   50
#define DD   300
#define HH   150
#define NCOL 1200   // 2 dirs * 600 gates
#define KP   320    // K padded (10 chunks of 32)
#define NP   1280   // N padded (10 chunks of 128)

// ---------------- static device scratch ----------------
#define GX0_OFF 0ULL
#define GXH_OFF 38400000ULL
#define GXH_SZ  96000000ULL
__device__ float g_gx[326400000];             // 1.31 GB
__device__ float g_gxc[640 * 1200];           // conv-LSTM gx
__device__ float g_sentreps[640 * 300];
__device__ float g_histreps[3 * 1600 * 300];
__device__ float g_u[32 * 300];
__device__ float g_WhhT[3 * 2 * 150 * 600];   // A_Whh transposed [m][dir][k][g]
__device__ float g_CWhhT[2 * 150 * 600];
__device__ float g_CWihT[303 * 1200];         // C_Wih transposed [d][c]
__device__ float g_bias2A[3 * 1200];          // bih + bhh (A)
__device__ float g_bias2C[1200];
__device__ int   g_slens[640];
__device__ int   g_hlens[1600];
__device__ int   g_clens[32];
__device__ int   g_sorder[640];               // indices sorted by len desc
__device__ int   g_horder[1600];
__device__ int   g_corder[32];
__device__ int   g_rowmap0[32000];            // valid (seq,t) -> orig row
__device__ int   g_rowmapH[80000];
__device__ int   g_vcount[2];
__device__ __nv_bfloat16 g_Ebf[50000 * KP];   // bf16 E, K-padded (32 MB)
__device__ __nv_bfloat16 g_Wbf[3 * NP * KP];  // bf16 Wih, [n][k] K-contiguous, padded

__device__ __forceinline__ float sigf(float x) { return 1.0f / (1.0f + __expf(-x)); }

__device__ __forceinline__ uint32_t smem_u32(const void* p) {
    uint32_t a;
    asm("{ .reg .u64 t; cvta.to.shared.u64 t, %1; cvt.u32.u64 %0, t; }" : "=r"(a) : "l"(p));
    return a;
}

#define CPA16(dst, src) asm volatile("cp.async.cg.shared.global [%0], [%1], 16;" :: "r"(dst), "l"(src) : "memory")
#define CPA_COMMIT()    asm volatile("cp.async.commit_group;" ::: "memory")
#define CPA_WAIT0()     asm volatile("cp.async.wait_group 0;" ::: "memory")
#define CPA_WAIT1()     asm volatile("cp.async.wait_group 1;" ::: "memory")
#define CPA_WAIT2()     asm volatile("cp.async.wait_group 2;" ::: "memory")

#define LDSM_X4(r0, r1, r2, r3, addr) \
    asm volatile("ldmatrix.sync.aligned.m8n8.x4.shared.b16 {%0,%1,%2,%3}, [%4];" \
        : "=r"(r0), "=r"(r1), "=r"(r2), "=r"(r3) : "r"(addr))

#define MMA16816(d, a0, a1, a2, a3, b0, b1) \
    asm volatile("mma.sync.aligned.m16n8k16.row.col.f32.bf16.bf16.f32 " \
        "{%0,%1,%2,%3},{%4,%5,%6,%7},{%8,%9},{%0,%1,%2,%3};" \
        : "+f"((d)[0]), "+f"((d)[1]), "+f"((d)[2]), "+f"((d)[3]) \
        : "r"(a0), "r"(a1), "r"(a2), "r"(a3), "r"(b0), "r"(b1))

// ---------------- setup: lengths, transposes, bias folds, bf16 conversion ----------------
__global__ void setup_kernel(const int* __restrict__ tc, const int* __restrict__ uh,
                             const float* __restrict__ E, const float* __restrict__ AWih,
                             const float* __restrict__ AWhh,
                             const float* __restrict__ Abih, const float* __restrict__ Abhh,
                             const float* __restrict__ CWih, const float* __restrict__ CWhh,
                             const float* __restrict__ Cbih, const float* __restrict__ Cbhh)
{
    int tid  = blockIdx.x * blockDim.x + threadIdx.x;
    int nthr = gridDim.x * blockDim.x;

    for (int i = tid; i < 50000 * KP; i += nthr) {
        int r = i / KP, col = i % KP;
        g_Ebf[i] = __float2bfloat16(col < 300 ? E[(size_t)r * 300 + col] : 0.0f);
    }
    for (int i = tid; i < 3 * NP * KP; i += nthr) {
        int mm = i / (NP * KP), r = (i / KP) % NP, col = i % KP;
        float v = (r < 1200 && col < 300) ? AWih[((size_t)mm * 1200 + r) * 300 + col] : 0.0f;
        g_Wbf[i] = __float2bfloat16(v);
    }
    for (int i = tid; i < 3 * 2 * 600 * 150; i += nthr) {
        int md = i / (600 * 150), r = i % (600 * 150);
        int g = r / 150, kk = r % 150;
        g_WhhT[(md * 150 + kk) * 600 + g] = AWhh[i];
    }
    for (int i = tid; i < 2 * 600 * 150; i += nthr) {
        int md = i / (600 * 150), r = i % (600 * 150);
        int g = r / 150, kk = r % 150;
        g_CWhhT[(md * 150 + kk) * 600 + g] = CWhh[i];
    }
    for (int i = tid; i < 1200 * 303; i += nthr) {
        int c = i / 303, d = i % 303;
        g_CWihT[d * 1200 + c] = CWih[i];
    }
    for (int i = tid; i < 3 * 1200; i += nthr) g_bias2A[i] = Abih[i] + Abhh[i];
    for (int i = tid; i < 1200; i += nthr)     g_bias2C[i] = Cbih[i] + Cbhh[i];

    for (int i = tid; i < 640; i += nthr) {
        int c = 0;
        for (int t = 0; t < SL; t++) c += (tc[i * 53 + 3 + t] != 0);
        g_slens[i] = c;
    }
    for (int i = tid; i < 1600; i += nthr) {
        int c = 0;
        for (int t = 0; t < SL; t++) c += (uh[i * 50 + t] != 0);
        g_hlens[i] = c;
    }
    for (int i = tid; i < 32; i += nthr) {
        int c = 0;
        for (int t = 0; t < NT; t++) c += (tc[(i * NT + t) * 53 + 3] != 0);
        g_clens[i] = c;
    }
}

// ---------------- sort: descending-length order + valid-row maps ----------------
__global__ void sort_kernel()
{
    __shared__ int sl[1600];
    __shared__ int soff[1601];
    int g = blockIdx.x;
    int n = (g == 0) ? 640 : ((g == 1) ? 1600 : 32);
    const int* lens = (g == 0) ? g_slens : ((g == 1) ? g_hlens : g_clens);
    int* order = (g == 0) ? g_sorder : ((g == 1) ? g_horder : g_corder);
    int tid = threadIdx.x;

    for (int i = tid; i < n; i += 256) sl[i] = lens[i];
    __syncthreads();

    // stable descending rank sort
    for (int i = tid; i < n; i += 256) {
        int li = sl[i], r = 0;
        for (int j = 0; j < n; j++) {
            int lj = sl[j];
            r += (lj > li) || (lj == li && j < i);
        }
        order[r] = i;
    }

    if (g < 2) {
        if (tid == 0) {
            int acc = 0;
            for (int i = 0; i < n; i++) { soff[i] = acc; acc += sl[i]; }
            g_vcount[g] = acc;
        }
        __syncthreads();
        int* rmap = (g == 0) ? g_rowmap0 : g_rowmapH;
        for (int i = tid; i < n; i += 256) {
            int off = soff[i], len = sl[i];
            for (int t = 0; t < len; t++) rmap[off + t] = i * 50 + t;
        }
    }
}

// ---------------- bf16 warp-MMA gx GEMM, A-resident, valid-row-compacted ----------------
#define SSTRIDE 40               // bf16 elements per row in smem (80 B)
#define ACH 10240                // bytes per A K-chunk (128 rows * 80 B)
#define BST 10240                // bytes per B stage
#define SM_B_OFF (10 * ACH)
#define GSM_BYTES (10 * ACH + 4 * BST)   // 143360

__global__ void __launch_bounds__(256) gx_mma(const int* __restrict__ tokb, int tstride, int toff,
                                              int nmats, unsigned long long gxbase,
                                              unsigned long long gxstride, int which)
{
    __shared__ int sRow[128];
    extern __shared__ char smem[];
    uint32_t sA = smem_u32(smem);
    uint32_t sB = sA + SM_B_OFF;

    int cnt = g_vcount[which];
    if (blockIdx.x * 128 >= cnt) return;
    const int* rmap = which ? g_rowmapH : g_rowmap0;

    int tid  = threadIdx.x;
    int lane = tid & 31, wid = tid >> 5;
    int wm = wid & 3, wn = wid >> 2;

    if (tid < 128) {
        int gi = blockIdx.x * 128 + tid;
        sRow[tid] = (gi < cnt) ? rmap[gi] : -1;
    }

    // ---- A gather (once): 128 valid rows x 320 bf16 ----
    int lrow = tid >> 1, hf = tid & 1;
    int gi = blockIdx.x * 128 + lrow;
    int tok = 0;
    if (gi < cnt) {
        int vrow = rmap[gi];
        int seq = vrow / 50, tt = vrow % 50;
        tok = tokb[seq * tstride + toff + tt];
    }
    const char* asrc = (const char*)(g_Ebf + (size_t)tok * KP);
#pragma unroll
    for (int ci = 0; ci < 5; ci++) {
        int c = ci * 2 + hf;
        uint32_t dst = sA + c * ACH + lrow * 80;
        const char* src = asrc + c * 64;
        CPA16(dst, src); CPA16(dst + 16, src + 16);
        CPA16(dst + 32, src + 32); CPA16(dst + 48, src + 48);
    }
    CPA_COMMIT();   // group: A

    int cofs = hf * 32;
    uint32_t dB0 = sB + lrow * 80 + cofs;
    int total = nmats * 100;

    // ---- prologue: B stages 0..2 ----
#pragma unroll
    for (int it = 0; it < 3; it++) {
        const char* src = (const char*)(g_Wbf + (size_t)lrow * KP + it * 32) + cofs;
        uint32_t dst = dB0 + it * BST;
        CPA16(dst, src); CPA16(dst + 16, src + 16);
        CPA_COMMIT();
    }

    int a_row  = wm * 32 + (lane & 15);
    int a_kofs = (lane >> 4) * 8;
    int b_row  = wn * 64 + ((lane >> 4) & 1) * 8 + (lane & 7);
    int b_kofs = ((lane >> 3) & 1) * 8;

    float acc[2][8][4];

#pragma unroll 1
    for (int it = 0; it < total; it++) {
        int k = it % 10;

        int rem = total - 1 - it;
        if (rem >= 2)      CPA_WAIT2();
        else if (rem == 1) CPA_WAIT1();
        else               CPA_WAIT0();
        __syncthreads();

        int itp = it + 3;
        if (itp < total) {
            int matp = itp / 100, ncp = (itp / 10) % 10, kp = itp % 10;
            const char* src = (const char*)(g_Wbf +
                ((size_t)matp * NP + ncp * 128 + lrow) * KP + kp * 32) + cofs;
            uint32_t dst = dB0 + (itp & 3) * BST;
            CPA16(dst, src); CPA16(dst + 16, src + 16);
            CPA_COMMIT();
        }

        if (k == 0) {
#pragma unroll
            for (int i = 0; i < 2; i++)
#pragma unroll
                for (int j = 0; j < 8; j++)
#pragma unroll
                    for (int q = 0; q < 4; q++) acc[i][j][q] = 0.0f;
        }

        uint32_t abase = sA + k * ACH;
        uint32_t bbase = sB + (it & 3) * BST;
#pragma unroll
        for (int ks = 0; ks < 2; ks++) {
            uint32_t afr[2][4];
#pragma unroll
            for (int mf = 0; mf < 2; mf++) {
                uint32_t addr = abase + (((a_row + mf * 16) * SSTRIDE) + ks * 16 + a_kofs) * 2;
                LDSM_X4(afr[mf][0], afr[mf][1], afr[mf][2], afr[mf][3], addr);
            }
            uint32_t bfr[4][4];
#pragma unroll
            for (int np = 0; np < 4; np++) {
                uint32_t addr = bbase + (((b_row + np * 16) * SSTRIDE) + ks * 16 + b_kofs) * 2;
                LDSM_X4(bfr[np][0], bfr[np][1], bfr[np][2], bfr[np][3], addr);
            }
#pragma unroll
            for (int mf = 0; mf < 2; mf++)
#pragma unroll
                for (int nf = 0; nf < 8; nf++) {
                    uint32_t b0 = bfr[nf >> 1][(nf & 1) * 2];
                    uint32_t b1 = bfr[nf >> 1][(nf & 1) * 2 + 1];
                    MMA16816(acc[mf][nf], afr[mf][0], afr[mf][1], afr[mf][2], afr[mf][3], b0, b1);
                }
        }

        if (k == 9) {
            int mat = it / 100, ncl = (it / 10) % 10;
            const float* bias = g_bias2A + mat * 1200;
            float* gxp = g_gx + gxbase + (size_t)mat * gxstride;
            int ocol0 = ncl * 128 + wn * 64 + (lane & 3) * 2;
#pragma unroll
            for (int mf = 0; mf < 2; mf++) {
                int r0i = wm * 32 + (lane >> 2) + mf * 16;
                int vr0 = sRow[r0i];        // tile row r  -> c0,c1
                int vr1 = sRow[r0i + 8];    // tile row r+8 -> c2,c3 (NOT vr0+8!)
                if (vr0 < 0 && vr1 < 0) continue;
#pragma unroll
                for (int nf = 0; nf < 8; nf++) {
                    int col = ocol0 + nf * 8;
                    if (col < 1200) {
                        float2 bv = *(const float2*)(bias + col);
                        if (vr0 >= 0)
                            *(float2*)(gxp + (size_t)vr0 * NCOL + col) =
                                make_float2(acc[mf][nf][0] + bv.x, acc[mf][nf][1] + bv.y);
                        if (vr1 >= 0)
                            *(float2*)(gxp + (size_t)vr1 * NCOL + col) =
                                make_float2(acc[mf][nf][2] + bv.x, acc[mf][nf][3] + bv.y);
                    }
                }
            }
        }
    }
}

// ---------------- conv-LSTM gx: feats[303] @ C_Wih^T + bias ----------------
__global__ void conv_gx_kernel(const int* __restrict__ tc)
{
    __shared__ float xs[8][304];
    int row0 = blockIdx.x * 8;
    int tid  = threadIdx.x;

    for (int i = tid; i < 8 * 300; i += 256) {
        int rr = i / 300, d = i % 300;
        xs[rr][d] = g_sentreps[(row0 + rr) * 300 + d];
    }
    if (tid < 24) {
        int rr = tid / 3, d = tid % 3;
        xs[rr][300 + d] = (float)tc[(row0 + rr) * 53 + d];
    }
    __syncthreads();

    for (int c = tid; c < NCOL; c += 256) {
        float a0 = g_bias2C[c], a1 = a0, a2 = a0, a3 = a0, a4 = a0, a5 = a0, a6 = a0, a7 = a0;
        for (int d = 0; d < 303; d++) {
            float w = g_CWihT[d * 1200 + c];
            a0 += xs[0][d] * w; a1 += xs[1][d] * w; a2 += xs[2][d] * w; a3 += xs[3][d] * w;
            a4 += xs[4][d] * w; a5 += xs[5][d] * w; a6 += xs[6][d] * w; a7 += xs[7][d] * w;
        }
        g_gxc[(size_t)(row0 + 0) * NCOL + c] = a0;
        g_gxc[(size_t)(row0 + 1) * NCOL + c] = a1;
        g_gxc[(size_t)(row0 + 2) * NCOL + c] = a2;
        g_gxc[(size_t)(row0 + 3) * NCOL + c] = a3;
        g_gxc[(size_t)(row0 + 4) * NCOL + c] = a4;
        g_gxc[(size_t)(row0 + 5) * NCOL + c] = a5;
        g_gxc[(size_t)(row0 + 6) * NCOL + c] = a6;
        g_gxc[(size_t)(row0 + 7) * NCOL + c] = a7;
    }
}

// ---------------- recurrent LSTM (persistent block, 16 sorted units, early exit) ----------------
__global__ void __launch_bounds__(160) lstm_recur_all(int conv)
{
    const float* WhhT; const float* gx; const int* lens; float* finals;
    const int* order;
    int nSeq, T, blk;
    if (conv) {
        WhhT = g_CWhhT; gx = g_gxc; lens = g_clens; finals = g_u; order = g_corder;
        nSeq = 32; T = 20; blk = blockIdx.x;
    } else {
        int b = blockIdx.x;
        T = 50;
        if (b < 80) {
            blk = b; nSeq = 640; WhhT = g_WhhT; gx = g_gx;
            lens = g_slens; finals = g_sentreps; order = g_sorder;
        } else {
            int g = (b - 80) / 200;
            blk = (b - 80) % 200; nSeq = 1600;
            WhhT = g_WhhT + (size_t)g * 2 * 150 * 600;
            gx = g_gx + GXH_OFF + (size_t)g * GXH_SZ;
            lens = g_hlens;
            finals = g_histreps + (size_t)g * 480000;
            order = g_horder;
        }
    }

    __shared__ float sh_h[16][160];
    __shared__ float sh_G[16][600];
    __shared__ int   sh_len[16], sh_seq[16];

    int tid = threadIdx.x;            // 160
    int u0  = blk * 16;
    int dir = (u0 >= nSeq) ? 1 : 0;   // nSeq is a multiple of 16

    if (tid < 16) {
        int idx = u0 + tid - dir * nSeq;
        int seq = order[idx];
        sh_seq[tid] = seq;
        sh_len[tid] = lens[seq];
    }
    for (int i = tid; i < 16 * 160; i += 160) ((float*)sh_h)[i] = 0.0f;
    __syncthreads();

    int Tmax = sh_len[0];             // descending order -> first is block max

    const float* Wb = WhhT + dir * 150 * 600;
    int gA = tid, gB = tid + 160, gC = tid + 320, gD = tid + 480;
    bool vD = (gD < 600);
    int  gDc = vD ? gD : 599;

    int uu = tid / 10;
    int j0 = (tid % 10) * 15;
    float c_reg[15];
#pragma unroll
    for (int m2 = 0; m2 < 15; m2++) c_reg[m2] = 0.0f;

    for (int s = 0; s < Tmax; s++) {
        float acc0[16], acc1[16], acc2[16], acc3[16];
#pragma unroll
        for (int u = 0; u < 16; u++) { acc0[u] = 0.f; acc1[u] = 0.f; acc2[u] = 0.f; acc3[u] = 0.f; }

#pragma unroll 2
        for (int k = 0; k < 150; k++) {
            const float* wr = Wb + k * 600;
            float w0 = wr[gA], w1 = wr[gB], w2 = wr[gC], w3 = wr[gDc];
#pragma unroll
            for (int u = 0; u < 16; u++) {
                float hv = sh_h[u][k];
                acc0[u] += w0 * hv; acc1[u] += w1 * hv; acc2[u] += w2 * hv; acc3[u] += w3 * hv;
            }
        }

#pragma unroll 1
        for (int u = 0; u < 16; u++) {
            int len = sh_len[u];
            if (s >= len) continue;
            int t = dir ? (len - 1 - s) : s;
            const float* gxr = gx + ((size_t)sh_seq[u] * T + t) * NCOL + dir * 600;
            sh_G[u][gA] = acc0[u] + gxr[gA];
            sh_G[u][gB] = acc1[u] + gxr[gB];
            sh_G[u][gC] = acc2[u] + gxr[gC];
            if (vD) sh_G[u][gD] = acc3[u] + gxr[gD];
        }
        __syncthreads();

        {
            int len = sh_len[uu];
            if (s < len) {
#pragma unroll
                for (int m2 = 0; m2 < 15; m2++) {
                    int j = j0 + m2;
                    float gi = sh_G[uu][j];
                    float gf = sh_G[uu][150 + j];
                    float gg = sh_G[uu][300 + j];
                    float go = sh_G[uu][450 + j];
                    float cc = sigf(gf) * c_reg[m2] + sigf(gi) * tanhf(gg);
                    c_reg[m2] = cc;
                    sh_h[uu][j] = sigf(go) * tanhf(cc);
                }
            }
        }
        __syncthreads();
    }

    {
        int seq = sh_seq[uu];
#pragma unroll
        for (int m2 = 0; m2 < 15; m2++) {
            int j = j0 + m2;
            finals[(size_t)seq * 300 + dir * 150 + j] = sh_h[uu][j];
        }
    }
}

// ---------------- memory hops + output head ----------------
__global__ void hops_kernel(const float* __restrict__ Wout, const float* __restrict__ bout,
                            float* __restrict__ out)
{
    int b = blockIdx.x;
    int tid = threadIdx.x;   // 128
    __shared__ float su[300];
    __shared__ float sc[50];
    __shared__ float wr[4];

    for (int d = tid; d < 300; d += 128) su[d] = g_u[b * 300 + d];
    __syncthreads();

    for (int hop = 0; hop < 2; hop++) {
        const float* rep0 = g_histreps + (size_t)hop * 1600 * 300 + (size_t)b * 50 * 300;
        const float* rep1 = g_histreps + (size_t)(hop + 1) * 1600 * 300 + (size_t)b * 50 * 300;
        int w = tid >> 5, l = tid & 31;
        for (int n = w; n < 50; n += 4) {
            const float* r = rep0 + n * 300;
            float s = 0.0f;
            for (int d = l; d < 300; d += 32) s += r[d] * su[d];
#pragma unroll
            for (int o = 16; o; o >>= 1) s += __shfl_xor_sync(0xffffffffu, s, o);
            if (l == 0) sc[n] = s;
        }
        __syncthreads();
        if (tid < 32) {
            float mx = -1e30f;
            for (int n = tid; n < 50; n += 32) mx = fmaxf(mx, sc[n]);
#pragma unroll
            for (int o = 16; o; o >>= 1) mx = fmaxf(mx, __shfl_xor_sync(0xffffffffu, mx, o));
            float sum = 0.0f;
            for (int n = tid; n < 50; n += 32) { float v = __expf(sc[n] - mx); sc[n] = v; sum += v; }
#pragma unroll
            for (int o = 16; o; o >>= 1) sum += __shfl_xor_sync(0xffffffffu, sum, o);
            float inv = 1.0f / sum;
            for (int n = tid; n < 50; n += 32) sc[n] *= inv;
        }
        __syncthreads();
        for (int d = tid; d < 300; d += 128) {
            float acc = su[d];
            for (int n = 0; n < 50; n++) acc += sc[n] * rep1[n * 300 + d];
            su[d] = acc;
        }
        __syncthreads();
    }

    float s = 0.0f;
    for (int d = tid; d < 300; d += 128) s += su[d] * Wout[d];
#pragma unroll
    for (int o = 16; o; o >>= 1) s += __shfl_xor_sync(0xffffffffu, s, o);
    if ((tid & 31) == 0) wr[tid >> 5] = s;
    __syncthreads();
    if (tid == 0) {
        float t = wr[0] + wr[1] + wr[2] + wr[3];
        out[b] = 1.0f / (1.0f + __expf(-(t + bout[0])));
    }
}

// ---------------- launch ----------------
extern "C" void kernel_launch(void* const* d_in, const int* in_sizes, int n_in,
                              void* d_out, int out_size)
{
    const int*   tc   = (const int*)d_in[0];
    const int*   uh   = (const int*)d_in[1];
    const float* E    = (const float*)d_in[2];
    const float* AWih = (const float*)d_in[3];
    const float* AWhh = (const float*)d_in[4];
    const float* Abih = (const float*)d_in[5];
    const float* Abhh = (const float*)d_in[6];
    const float* CWih = (const float*)d_in[7];
    const float* CWhh = (const float*)d_in[8];
    const float* Cbih = (const float*)d_in[9];
    const float* Cbhh = (const float*)d_in[10];
    const float* Wout = (const float*)d_in[11];
    const float* bout = (const float*)d_in[12];
    float* out = (float*)d_out;

    cudaFuncSetAttribute(gx_mma, cudaFuncAttributeMaxDynamicSharedMemorySize, GSM_BYTES);

    setup_kernel<<<264, 256>>>(tc, uh, E, AWih, AWhh, Abih, Abhh, CWih, CWhh, Cbih, Cbhh);
    sort_kernel<<<3, 256>>>();

    // target sentences: A[0] only; history: all 3 matrices per A-tile
    gx_mma<<<250, 256, GSM_BYTES>>>(tc, 53, 3, 1, GX0_OFF, 0ULL, 0);
    gx_mma<<<625, 256, GSM_BYTES>>>(uh, 50, 0, 3, GXH_OFF, GXH_SZ, 1);

    // all big recurrences in one launch (80 + 3*200 blocks)
    lstm_recur_all<<<680, 160>>>(0);

    // conversation-level biLSTM
    conv_gx_kernel<<<80, 256>>>(tc);
    lstm_recur_all<<<4, 160>>>(1);

    // memory hops + head
    hops_kernel<<<32, 128>>>(Wout, bout, out);
    (void)in_sizes; (void)n_in; (void)out_size;
}

// round 8
// speedup vs baseline: 3.5128x; 1.0651x over previous
#include <cuda_runtime.h>
#include <cuda_bf16.h>
#include <math.h>
#include <stdint.h>

// Problem constants
#define BB   32
#define NT   20
#define SL   50
#define DD   300
#define HH   150
#define NCOL 1200   // 2 dirs * 600 gates
#define KP   320    // K padded (10 chunks of 32)
#define NP   1280   // N padded (10 chunks of 128)

// ---------------- static device scratch ----------------
#define GX0_OFF 0ULL
#define GXH_OFF 38400000ULL
#define GXH_SZ  96000000ULL
__device__ float g_gx[326400000];             // 1.31 GB
__device__ float g_gxc[640 * 1200];           // conv-LSTM gx
__device__ float g_sentreps[640 * 300];
__device__ float g_histreps[3 * 1600 * 300];
__device__ float g_u[32 * 300];
__device__ float g_WhhT[3 * 2 * 150 * 600];   // A_Whh transposed [m][dir][k][g]
__device__ float g_CWhhT[2 * 150 * 600];
__device__ float g_CWihT[303 * 1200];         // C_Wih transposed [d][c]
__device__ float g_bias2A[3 * 1200];          // bih + bhh (A)
__device__ float g_bias2C[1200];
__device__ int   g_slens[640];
__device__ int   g_hlens[1600];
__device__ int   g_clens[32];
__device__ int   g_sorder[640];               // indices sorted by len desc
__device__ int   g_horder[1600];
__device__ int   g_corder[32];
__device__ int   g_rowmap0[32000];            // valid (seq,t) -> orig row
__device__ int   g_rowmapH[80000];
__device__ int   g_vcount[2];
__device__ __nv_bfloat16 g_Ebf[50000 * KP];   // bf16 E, K-padded (32 MB)
__device__ __nv_bfloat16 g_Wbf[3 * NP * KP];  // bf16 Wih, [n][k] K-contiguous, padded

__device__ __forceinline__ float sigf(float x) { return 1.0f / (1.0f + __expf(-x)); }

__device__ __forceinline__ uint32_t smem_u32(const void* p) {
    uint32_t a;
    asm("{ .reg .u64 t; cvta.to.shared.u64 t, %1; cvt.u32.u64 %0, t; }" : "=r"(a) : "l"(p));
    return a;
}

// packed fp32x2 helpers (Blackwell dual-fp32)
__device__ __forceinline__ unsigned long long pack2(float x) {
    unsigned long long r;
    asm("mov.b64 %0, {%1, %1};" : "=l"(r) : "f"(x));
    return r;
}
__device__ __forceinline__ void fma2(unsigned long long& d, unsigned long long a, unsigned long long b) {
    asm("fma.rn.f32x2 %0, %1, %2, %0;" : "+l"(d) : "l"(a), "l"(b));
}
__device__ __forceinline__ void unpack2(unsigned long long v, float& lo, float& hi) {
    asm("mov.b64 {%0, %1}, %2;" : "=f"(lo), "=f"(hi) : "l"(v));
}
__device__ __forceinline__ unsigned long long lds64(uint32_t addr) {
    unsigned long long v;
    asm volatile("ld.shared.b64 %0, [%1];" : "=l"(v) : "r"(addr));
    return v;
}

#define CPA16(dst, src) asm volatile("cp.async.cg.shared.global [%0], [%1], 16;" :: "r"(dst), "l"(src) : "memory")
#define CPA_COMMIT()    asm volatile("cp.async.commit_group;" ::: "memory")
#define CPA_WAIT0()     asm volatile("cp.async.wait_group 0;" ::: "memory")
#define CPA_WAIT1()     asm volatile("cp.async.wait_group 1;" ::: "memory")
#define CPA_WAIT2()     asm volatile("cp.async.wait_group 2;" ::: "memory")

#define LDSM_X4(r0, r1, r2, r3, addr) \
    asm volatile("ldmatrix.sync.aligned.m8n8.x4.shared.b16 {%0,%1,%2,%3}, [%4];" \
        : "=r"(r0), "=r"(r1), "=r"(r2), "=r"(r3) : "r"(addr))

#define MMA16816(d, a0, a1, a2, a3, b0, b1) \
    asm volatile("mma.sync.aligned.m16n8k16.row.col.f32.bf16.bf16.f32 " \
        "{%0,%1,%2,%3},{%4,%5,%6,%7},{%8,%9},{%0,%1,%2,%3};" \
        : "+f"((d)[0]), "+f"((d)[1]), "+f"((d)[2]), "+f"((d)[3]) \
        : "r"(a0), "r"(a1), "r"(a2), "r"(a3), "r"(b0), "r"(b1))

// ---------------- setup: lengths, transposes, bias folds, bf16 conversion ----------------
__global__ void setup_kernel(const int* __restrict__ tc, const int* __restrict__ uh,
                             const float* __restrict__ E, const float* __restrict__ AWih,
                             const float* __restrict__ AWhh,
                             const float* __restrict__ Abih, const float* __restrict__ Abhh,
                             const float* __restrict__ CWih, const float* __restrict__ CWhh,
                             const float* __restrict__ Cbih, const float* __restrict__ Cbhh)
{
    int tid  = blockIdx.x * blockDim.x + threadIdx.x;
    int nthr = gridDim.x * blockDim.x;

    for (int i = tid; i < 50000 * KP; i += nthr) {
        int r = i / KP, col = i % KP;
        g_Ebf[i] = __float2bfloat16(col < 300 ? E[(size_t)r * 300 + col] : 0.0f);
    }
    for (int i = tid; i < 3 * NP * KP; i += nthr) {
        int mm = i / (NP * KP), r = (i / KP) % NP, col = i % KP;
        float v = (r < 1200 && col < 300) ? AWih[((size_t)mm * 1200 + r) * 300 + col] : 0.0f;
        g_Wbf[i] = __float2bfloat16(v);
    }
    for (int i = tid; i < 3 * 2 * 600 * 150; i += nthr) {
        int md = i / (600 * 150), r = i % (600 * 150);
        int g = r / 150, kk = r % 150;
        g_WhhT[(md * 150 + kk) * 600 + g] = AWhh[i];
    }
    for (int i = tid; i < 2 * 600 * 150; i += nthr) {
        int md = i / (600 * 150), r = i % (600 * 150);
        int g = r / 150, kk = r % 150;
        g_CWhhT[(md * 150 + kk) * 600 + g] = CWhh[i];
    }
    for (int i = tid; i < 1200 * 303; i += nthr) {
        int c = i / 303, d = i % 303;
        g_CWihT[d * 1200 + c] = CWih[i];
    }
    for (int i = tid; i < 3 * 1200; i += nthr) g_bias2A[i] = Abih[i] + Abhh[i];
    for (int i = tid; i < 1200; i += nthr)     g_bias2C[i] = Cbih[i] + Cbhh[i];

    for (int i = tid; i < 640; i += nthr) {
        int c = 0;
        for (int t = 0; t < SL; t++) c += (tc[i * 53 + 3 + t] != 0);
        g_slens[i] = c;
    }
    for (int i = tid; i < 1600; i += nthr) {
        int c = 0;
        for (int t = 0; t < SL; t++) c += (uh[i * 50 + t] != 0);
        g_hlens[i] = c;
    }
    for (int i = tid; i < 32; i += nthr) {
        int c = 0;
        for (int t = 0; t < NT; t++) c += (tc[(i * NT + t) * 53 + 3] != 0);
        g_clens[i] = c;
    }
}

// ---------------- sort: descending-length order + valid-row maps ----------------
__global__ void sort_kernel()
{
    __shared__ int sl[1600];
    __shared__ int soff[1601];
    int g = blockIdx.x;
    int n = (g == 0) ? 640 : ((g == 1) ? 1600 : 32);
    const int* lens = (g == 0) ? g_slens : ((g == 1) ? g_hlens : g_clens);
    int* order = (g == 0) ? g_sorder : ((g == 1) ? g_horder : g_corder);
    int tid = threadIdx.x;

    for (int i = tid; i < n; i += 256) sl[i] = lens[i];
    __syncthreads();

    // stable descending rank sort
    for (int i = tid; i < n; i += 256) {
        int li = sl[i], r = 0;
        for (int j = 0; j < n; j++) {
            int lj = sl[j];
            r += (lj > li) || (lj == li && j < i);
        }
        order[r] = i;
    }

    if (g < 2) {
        if (tid == 0) {
            int acc = 0;
            for (int i = 0; i < n; i++) { soff[i] = acc; acc += sl[i]; }
            g_vcount[g] = acc;
        }
        __syncthreads();
        int* rmap = (g == 0) ? g_rowmap0 : g_rowmapH;
        for (int i = tid; i < n; i += 256) {
            int off = soff[i], len = sl[i];
            for (int t = 0; t < len; t++) rmap[off + t] = i * 50 + t;
        }
    }
}

// ---------------- bf16 warp-MMA gx GEMM, A-resident, valid-row-compacted, fused ----------------
#define SSTRIDE 40               // bf16 elements per row in smem (80 B)
#define ACH 10240                // bytes per A K-chunk (128 rows * 80 B)
#define BST 10240                // bytes per B stage
#define SM_B_OFF (10 * ACH)
#define GSM_BYTES (10 * ACH + 4 * BST)   // 143360

__global__ void __launch_bounds__(256) gx_mma(const int* __restrict__ tc, const int* __restrict__ uh)
{
    __shared__ int sRow[128];
    extern __shared__ char smem[];
    uint32_t sA = smem_u32(smem);
    uint32_t sB = sA + SM_B_OFF;

    // block -> (target | history) subproblem
    const int* tokb; int tstride, toff, nmats, which, blk;
    unsigned long long gxbase, gxstride;
    if (blockIdx.x < 250) {
        tokb = tc; tstride = 53; toff = 3; nmats = 1; which = 0; blk = blockIdx.x;
        gxbase = GX0_OFF; gxstride = 0ULL;
    } else {
        tokb = uh; tstride = 50; toff = 0; nmats = 3; which = 1; blk = blockIdx.x - 250;
        gxbase = GXH_OFF; gxstride = GXH_SZ;
    }

    int cnt = g_vcount[which];
    if (blk * 128 >= cnt) return;
    const int* rmap = which ? g_rowmapH : g_rowmap0;

    int tid  = threadIdx.x;
    int lane = tid & 31, wid = tid >> 5;
    int wm = wid & 3, wn = wid >> 2;

    if (tid < 128) {
        int gi = blk * 128 + tid;
        sRow[tid] = (gi < cnt) ? rmap[gi] : -1;
    }

    // ---- A gather (once): 128 valid rows x 320 bf16 ----
    int lrow = tid >> 1, hf = tid & 1;
    int gi = blk * 128 + lrow;
    int tok = 0;
    if (gi < cnt) {
        int vrow = rmap[gi];
        int seq = vrow / 50, tt = vrow % 50;
        tok = tokb[seq * tstride + toff + tt];
    }
    const char* asrc = (const char*)(g_Ebf + (size_t)tok * KP);
#pragma unroll
    for (int ci = 0; ci < 5; ci++) {
        int c = ci * 2 + hf;
        uint32_t dst = sA + c * ACH + lrow * 80;
        const char* src = asrc + c * 64;
        CPA16(dst, src); CPA16(dst + 16, src + 16);
        CPA16(dst + 32, src + 32); CPA16(dst + 48, src + 48);
    }
    CPA_COMMIT();   // group: A

    int cofs = hf * 32;
    uint32_t dB0 = sB + lrow * 80 + cofs;
    int total = nmats * 100;

    // ---- prologue: B stages 0..2 ----
#pragma unroll
    for (int it = 0; it < 3; it++) {
        const char* src = (const char*)(g_Wbf + (size_t)lrow * KP + it * 32) + cofs;
        uint32_t dst = dB0 + it * BST;
        CPA16(dst, src); CPA16(dst + 16, src + 16);
        CPA_COMMIT();
    }

    int a_row  = wm * 32 + (lane & 15);
    int a_kofs = (lane >> 4) * 8;
    int b_row  = wn * 64 + ((lane >> 4) & 1) * 8 + (lane & 7);
    int b_kofs = ((lane >> 3) & 1) * 8;

    float acc[2][8][4];

#pragma unroll 1
    for (int it = 0; it < total; it++) {
        int k = it % 10;

        int rem = total - 1 - it;
        if (rem >= 2)      CPA_WAIT2();
        else if (rem == 1) CPA_WAIT1();
        else               CPA_WAIT0();
        __syncthreads();

        int itp = it + 3;
        if (itp < total) {
            int matp = itp / 100, ncp = (itp / 10) % 10, kp = itp % 10;
            const char* src = (const char*)(g_Wbf +
                ((size_t)matp * NP + ncp * 128 + lrow) * KP + kp * 32) + cofs;
            uint32_t dst = dB0 + (itp & 3) * BST;
            CPA16(dst, src); CPA16(dst + 16, src + 16);
            CPA_COMMIT();
        }

        if (k == 0) {
#pragma unroll
            for (int i = 0; i < 2; i++)
#pragma unroll
                for (int j = 0; j < 8; j++)
#pragma unroll
                    for (int q = 0; q < 4; q++) acc[i][j][q] = 0.0f;
        }

        uint32_t abase = sA + k * ACH;
        uint32_t bbase = sB + (it & 3) * BST;
#pragma unroll
        for (int ks = 0; ks < 2; ks++) {
            uint32_t afr[2][4];
#pragma unroll
            for (int mf = 0; mf < 2; mf++) {
                uint32_t addr = abase + (((a_row + mf * 16) * SSTRIDE) + ks * 16 + a_kofs) * 2;
                LDSM_X4(afr[mf][0], afr[mf][1], afr[mf][2], afr[mf][3], addr);
            }
            uint32_t bfr[4][4];
#pragma unroll
            for (int np = 0; np < 4; np++) {
                uint32_t addr = bbase + (((b_row + np * 16) * SSTRIDE) + ks * 16 + b_kofs) * 2;
                LDSM_X4(bfr[np][0], bfr[np][1], bfr[np][2], bfr[np][3], addr);
            }
#pragma unroll
            for (int mf = 0; mf < 2; mf++)
#pragma unroll
                for (int nf = 0; nf < 8; nf++) {
                    uint32_t b0 = bfr[nf >> 1][(nf & 1) * 2];
                    uint32_t b1 = bfr[nf >> 1][(nf & 1) * 2 + 1];
                    MMA16816(acc[mf][nf], afr[mf][0], afr[mf][1], afr[mf][2], afr[mf][3], b0, b1);
                }
        }

        if (k == 9) {
            int mat = it / 100, ncl = (it / 10) % 10;
            const float* bias = g_bias2A + mat * 1200;
            float* gxp = g_gx + gxbase + (size_t)mat * gxstride;
            int ocol0 = ncl * 128 + wn * 64 + (lane & 3) * 2;
#pragma unroll
            for (int mf = 0; mf < 2; mf++) {
                int r0i = wm * 32 + (lane >> 2) + mf * 16;
                int vr0 = sRow[r0i];        // tile row r   -> c0,c1
                int vr1 = sRow[r0i + 8];    // tile row r+8 -> c2,c3
                if (vr0 < 0 && vr1 < 0) continue;
#pragma unroll
                for (int nf = 0; nf < 8; nf++) {
                    int col = ocol0 + nf * 8;
                    if (col < 1200) {
                        float2 bv = *(const float2*)(bias + col);
                        if (vr0 >= 0)
                            *(float2*)(gxp + (size_t)vr0 * NCOL + col) =
                                make_float2(acc[mf][nf][0] + bv.x, acc[mf][nf][1] + bv.y);
                        if (vr1 >= 0)
                            *(float2*)(gxp + (size_t)vr1 * NCOL + col) =
                                make_float2(acc[mf][nf][2] + bv.x, acc[mf][nf][3] + bv.y);
                    }
                }
            }
        }
    }
}

// ---------------- conv-LSTM gx: feats[303] @ C_Wih^T + bias ----------------
__global__ void conv_gx_kernel(const int* __restrict__ tc)
{
    __shared__ float xs[8][304];
    int row0 = blockIdx.x * 8;
    int tid  = threadIdx.x;

    for (int i = tid; i < 8 * 300; i += 256) {
        int rr = i / 300, d = i % 300;
        xs[rr][d] = g_sentreps[(row0 + rr) * 300 + d];
    }
    if (tid < 24) {
        int rr = tid / 3, d = tid % 3;
        xs[rr][300 + d] = (float)tc[(row0 + rr) * 53 + d];
    }
    __syncthreads();

    for (int c = tid; c < NCOL; c += 256) {
        float a0 = g_bias2C[c], a1 = a0, a2 = a0, a3 = a0, a4 = a0, a5 = a0, a6 = a0, a7 = a0;
        for (int d = 0; d < 303; d++) {
            float w = g_CWihT[d * 1200 + c];
            a0 += xs[0][d] * w; a1 += xs[1][d] * w; a2 += xs[2][d] * w; a3 += xs[3][d] * w;
            a4 += xs[4][d] * w; a5 += xs[5][d] * w; a6 += xs[6][d] * w; a7 += xs[7][d] * w;
        }
        g_gxc[(size_t)(row0 + 0) * NCOL + c] = a0;
        g_gxc[(size_t)(row0 + 1) * NCOL + c] = a1;
        g_gxc[(size_t)(row0 + 2) * NCOL + c] = a2;
        g_gxc[(size_t)(row0 + 3) * NCOL + c] = a3;
        g_gxc[(size_t)(row0 + 4) * NCOL + c] = a4;
        g_gxc[(size_t)(row0 + 5) * NCOL + c] = a5;
        g_gxc[(size_t)(row0 + 6) * NCOL + c] = a6;
        g_gxc[(size_t)(row0 + 7) * NCOL + c] = a7;
    }
}

// ---------------- recurrent LSTM (persistent, sorted, early exit, f32x2 GEMV) ----------------
__global__ void __launch_bounds__(160) lstm_recur_all(int conv)
{
    const float* WhhT; const float* gx; const int* lens; float* finals;
    const int* order;
    int nSeq, T, blk;
    if (conv) {
        WhhT = g_CWhhT; gx = g_gxc; lens = g_clens; finals = g_u; order = g_corder;
        nSeq = 32; T = 20; blk = blockIdx.x;
    } else {
        int b = blockIdx.x;
        T = 50;
        if (b < 80) {
            blk = b; nSeq = 640; WhhT = g_WhhT; gx = g_gx;
            lens = g_slens; finals = g_sentreps; order = g_sorder;
        } else {
            int g = (b - 80) / 200;
            blk = (b - 80) % 200; nSeq = 1600;
            WhhT = g_WhhT + (size_t)g * 2 * 150 * 600;
            gx = g_gx + GXH_OFF + (size_t)g * GXH_SZ;
            lens = g_hlens;
            finals = g_histreps + (size_t)g * 480000;
            order = g_horder;
        }
    }

    __shared__ float sh_h[150][16];    // transposed: [hidden-k][unit]
    __shared__ float sh_G[16][600];
    __shared__ int   sh_len[16], sh_seq[16];

    int tid = threadIdx.x;            // 160
    int u0  = blk * 16;
    int dir = (u0 >= nSeq) ? 1 : 0;   // nSeq is a multiple of 16

    if (tid < 16) {
        int idx = u0 + tid - dir * nSeq;
        int seq = order[idx];
        sh_seq[tid] = seq;
        sh_len[tid] = lens[seq];
    }
    for (int i = tid; i < 150 * 16; i += 160) ((float*)sh_h)[i] = 0.0f;
    __syncthreads();

    int Tmax = sh_len[0];             // descending order -> first is block max

    const float* Wb = WhhT + dir * 150 * 600;
    int gA = tid, gB = tid + 160, gC = tid + 320, gD = tid + 480;
    bool vD = (gD < 600);
    int  gDc = vD ? gD : 599;

    uint32_t shh = smem_u32(sh_h);

    int uu = tid / 10;
    int j0 = (tid % 10) * 15;
    float c_reg[15];
#pragma unroll
    for (int m2 = 0; m2 < 15; m2++) c_reg[m2] = 0.0f;

    for (int s = 0; s < Tmax; s++) {
        unsigned long long acc2[4][8];
#pragma unroll
        for (int g = 0; g < 4; g++)
#pragma unroll
            for (int p = 0; p < 8; p++) acc2[g][p] = 0ULL;

#pragma unroll 2
        for (int k = 0; k < 150; k++) {
            const float* wr = Wb + k * 600;
            unsigned long long W0 = pack2(wr[gA]);
            unsigned long long W1 = pack2(wr[gB]);
            unsigned long long W2 = pack2(wr[gC]);
            unsigned long long W3 = pack2(wr[gDc]);
            uint32_t hbase = shh + k * 64;
#pragma unroll
            for (int p = 0; p < 8; p++) {
                unsigned long long H = lds64(hbase + p * 8);
                fma2(acc2[0][p], W0, H);
                fma2(acc2[1][p], W1, H);
                fma2(acc2[2][p], W2, H);
                fma2(acc2[3][p], W3, H);
            }
        }

#pragma unroll 1
        for (int p = 0; p < 8; p++) {
            float a0l, a0h, a1l, a1h, a2l, a2h, a3l, a3h;
            unpack2(acc2[0][p], a0l, a0h);
            unpack2(acc2[1][p], a1l, a1h);
            unpack2(acc2[2][p], a2l, a2h);
            unpack2(acc2[3][p], a3l, a3h);
#pragma unroll
            for (int half = 0; half < 2; half++) {
                int u = 2 * p + half;
                int len = sh_len[u];
                if (s >= len) continue;
                int t = dir ? (len - 1 - s) : s;
                const float* gxr = gx + ((size_t)sh_seq[u] * T + t) * NCOL + dir * 600;
                sh_G[u][gA] = (half ? a0h : a0l) + gxr[gA];
                sh_G[u][gB] = (half ? a1h : a1l) + gxr[gB];
                sh_G[u][gC] = (half ? a2h : a2l) + gxr[gC];
                if (vD) sh_G[u][gD] = (half ? a3h : a3l) + gxr[gD];
            }
        }
        __syncthreads();

        {
            int len = sh_len[uu];
            if (s < len) {
#pragma unroll
                for (int m2 = 0; m2 < 15; m2++) {
                    int j = j0 + m2;
                    float gi = sh_G[uu][j];
                    float gf = sh_G[uu][150 + j];
                    float gg = sh_G[uu][300 + j];
                    float go = sh_G[uu][450 + j];
                    float cc = sigf(gf) * c_reg[m2] + sigf(gi) * tanhf(gg);
                    c_reg[m2] = cc;
                    sh_h[j][uu] = sigf(go) * tanhf(cc);
                }
            }
        }
        __syncthreads();
    }

    {
        int seq = sh_seq[uu];
#pragma unroll
        for (int m2 = 0; m2 < 15; m2++) {
            int j = j0 + m2;
            finals[(size_t)seq * 300 + dir * 150 + j] = sh_h[j][uu];
        }
    }
}

// ---------------- memory hops + output head ----------------
__global__ void hops_kernel(const float* __restrict__ Wout, const float* __restrict__ bout,
                            float* __restrict__ out)
{
    int b = blockIdx.x;
    int tid = threadIdx.x;   // 128
    __shared__ float su[300];
    __shared__ float sc[50];
    __shared__ float wr[4];

    for (int d = tid; d < 300; d += 128) su[d] = g_u[b * 300 + d];
    __syncthreads();

    for (int hop = 0; hop < 2; hop++) {
        const float* rep0 = g_histreps + (size_t)hop * 1600 * 300 + (size_t)b * 50 * 300;
        const float* rep1 = g_histreps + (size_t)(hop + 1) * 1600 * 300 + (size_t)b * 50 * 300;
        int w = tid >> 5, l = tid & 31;
        for (int n = w; n < 50; n += 4) {
            const float* r = rep0 + n * 300;
            float s = 0.0f;
            for (int d = l; d < 300; d += 32) s += r[d] * su[d];
#pragma unroll
            for (int o = 16; o; o >>= 1) s += __shfl_xor_sync(0xffffffffu, s, o);
            if (l == 0) sc[n] = s;
        }
        __syncthreads();
        if (tid < 32) {
            float mx = -1e30f;
            for (int n = tid; n < 50; n += 32) mx = fmaxf(mx, sc[n]);
#pragma unroll
            for (int o = 16; o; o >>= 1) mx = fmaxf(mx, __shfl_xor_sync(0xffffffffu, mx, o));
            float sum = 0.0f;
            for (int n = tid; n < 50; n += 32) { float v = __expf(sc[n] - mx); sc[n] = v; sum += v; }
#pragma unroll
            for (int o = 16; o; o >>= 1) sum += __shfl_xor_sync(0xffffffffu, sum, o);
            float inv = 1.0f / sum;
            for (int n = tid; n < 50; n += 32) sc[n] *= inv;
        }
        __syncthreads();
        for (int d = tid; d < 300; d += 128) {
            float acc = su[d];
            for (int n = 0; n < 50; n++) acc += sc[n] * rep1[n * 300 + d];
            su[d] = acc;
        }
        __syncthreads();
    }

    float s = 0.0f;
    for (int d = tid; d < 300; d += 128) s += su[d] * Wout[d];
#pragma unroll
    for (int o = 16; o; o >>= 1) s += __shfl_xor_sync(0xffffffffu, s, o);
    if ((tid & 31) == 0) wr[tid >> 5] = s;
    __syncthreads();
    if (tid == 0) {
        float t = wr[0] + wr[1] + wr[2] + wr[3];
        out[b] = 1.0f / (1.0f + __expf(-(t + bout[0])));
    }
}

// ---------------- launch ----------------
extern "C" void kernel_launch(void* const* d_in, const int* in_sizes, int n_in,
                              void* d_out, int out_size)
{
    const int*   tc   = (const int*)d_in[0];
    const int*   uh   = (const int*)d_in[1];
    const float* E    = (const float*)d_in[2];
    const float* AWih = (const float*)d_in[3];
    const float* AWhh = (const float*)d_in[4];
    const float* Abih = (const float*)d_in[5];
    const float* Abhh = (const float*)d_in[6];
    const float* CWih = (const float*)d_in[7];
    const float* CWhh = (const float*)d_in[8];
    const float* Cbih = (const float*)d_in[9];
    const float* Cbhh = (const float*)d_in[10];
    const float* Wout = (const float*)d_in[11];
    const float* bout = (const float*)d_in[12];
    float* out = (float*)d_out;

    cudaFuncSetAttribute(gx_mma, cudaFuncAttributeMaxDynamicSharedMemorySize, GSM_BYTES);

    setup_kernel<<<264, 256>>>(tc, uh, E, AWih, AWhh, Abih, Abhh, CWih, CWhh, Cbih, Cbhh);
    sort_kernel<<<3, 256>>>();

    // fused: blocks 0..249 target (A[0]), 250..874 history (all 3 matrices)
    gx_mma<<<875, 256, GSM_BYTES>>>(tc, uh);

    // all big recurrences in one launch (80 + 3*200 blocks)
    lstm_recur_all<<<680, 160>>>(0);

    // conversation-level biLSTM
    conv_gx_kernel<<<80, 256>>>(tc);
    lstm_recur_all<<<4, 160>>>(1);

    // memory hops + head
    hops_kernel<<<32, 128>>>(Wout, bout, out);
    (void)in_sizes; (void)n_in; (void)out_size;
}

// round 9
// speedup vs baseline: 4.0627x; 1.1565x over previous
#include <cuda_runtime.h>
#include <cuda_bf16.h>
#include <math.h>
#include <stdint.h>

// Problem constants
#define BB   32
#define NT   20
#define SL   50
#define DD   300
#define HH   150
#define NCOL 1200   // 2 dirs * 600 gates
#define KP   320    // K padded (10 chunks of 32)
#define NP   1280   // N padded (10 chunks of 128)

// ---------------- static device scratch ----------------
#define GX0_OFF 0ULL
#define GXH_OFF 38400000ULL
#define GXH_SZ  96000000ULL
__device__ float g_gx[326400000];             // 1.31 GB
__device__ float g_gxc[640 * 1200];           // conv-LSTM gx
__device__ float g_sentreps[640 * 300];
__device__ float g_histreps[3 * 1600 * 300];
__device__ float g_u[32 * 300];
__device__ float g_WhhP[8 * 150 * 640];       // packed recur weights [md][k][tid][4]
__device__ float g_CWihT[303 * 1200];         // C_Wih transposed [d][c]
__device__ float g_bias2A[3 * 1200];          // bih + bhh (A)
__device__ float g_bias2C[1200];
__device__ int   g_slens[640];
__device__ int   g_hlens[1600];
__device__ int   g_clens[32];
__device__ int   g_sorder[640];               // indices sorted by len desc
__device__ int   g_horder[1600];
__device__ int   g_corder[32];
__device__ int   g_rowmap0[32000];            // valid (seq,t) -> orig row
__device__ int   g_rowmapH[80000];
__device__ int   g_vcount[2];
__device__ __nv_bfloat16 g_Ebf[50000 * KP];   // bf16 E, K-padded (32 MB)
__device__ __nv_bfloat16 g_Wbf[3 * NP * KP];  // bf16 Wih, [n][k] K-contiguous, padded

__device__ __forceinline__ float sigf(float x) { return 1.0f / (1.0f + __expf(-x)); }

__device__ __forceinline__ uint32_t smem_u32(const void* p) {
    uint32_t a;
    asm("{ .reg .u64 t; cvta.to.shared.u64 t, %1; cvt.u32.u64 %0, t; }" : "=r"(a) : "l"(p));
    return a;
}

// packed fp32x2 helpers (Blackwell dual-fp32)
__device__ __forceinline__ unsigned long long pack2(float x) {
    unsigned long long r;
    asm("mov.b64 %0, {%1, %1};" : "=l"(r) : "f"(x));
    return r;
}
__device__ __forceinline__ void fma2(unsigned long long& d, unsigned long long a, unsigned long long b) {
    asm("fma.rn.f32x2 %0, %1, %2, %0;" : "+l"(d) : "l"(a), "l"(b));
}
__device__ __forceinline__ void unpack2(unsigned long long v, float& lo, float& hi) {
    asm("mov.b64 {%0, %1}, %2;" : "=f"(lo), "=f"(hi) : "l"(v));
}
__device__ __forceinline__ unsigned long long lds64(uint32_t addr) {
    unsigned long long v;
    asm volatile("ld.shared.b64 %0, [%1];" : "=l"(v) : "r"(addr));
    return v;
}

#define CPA16(dst, src) asm volatile("cp.async.cg.shared.global [%0], [%1], 16;" :: "r"(dst), "l"(src) : "memory")
#define CPA_COMMIT()    asm volatile("cp.async.commit_group;" ::: "memory")
#define CPA_WAIT0()     asm volatile("cp.async.wait_group 0;" ::: "memory")
#define CPA_WAIT1()     asm volatile("cp.async.wait_group 1;" ::: "memory")
#define CPA_WAIT2()     asm volatile("cp.async.wait_group 2;" ::: "memory")

#define LDSM_X4(r0, r1, r2, r3, addr) \
    asm volatile("ldmatrix.sync.aligned.m8n8.x4.shared.b16 {%0,%1,%2,%3}, [%4];" \
        : "=r"(r0), "=r"(r1), "=r"(r2), "=r"(r3) : "r"(addr))

#define MMA16816(d, a0, a1, a2, a3, b0, b1) \
    asm volatile("mma.sync.aligned.m16n8k16.row.col.f32.bf16.bf16.f32 " \
        "{%0,%1,%2,%3},{%4,%5,%6,%7},{%8,%9},{%0,%1,%2,%3};" \
        : "+f"((d)[0]), "+f"((d)[1]), "+f"((d)[2]), "+f"((d)[3]) \
        : "r"(a0), "r"(a1), "r"(a2), "r"(a3), "r"(b0), "r"(b1))

// ---------------- setup: lengths, packs, bias folds, bf16 conversion ----------------
__global__ void setup_kernel(const int* __restrict__ tc, const int* __restrict__ uh,
                             const float* __restrict__ E, const float* __restrict__ AWih,
                             const float* __restrict__ AWhh,
                             const float* __restrict__ Abih, const float* __restrict__ Abhh,
                             const float* __restrict__ CWih, const float* __restrict__ CWhh,
                             const float* __restrict__ Cbih, const float* __restrict__ Cbhh)
{
    int tid  = blockIdx.x * blockDim.x + threadIdx.x;
    int nthr = gridDim.x * blockDim.x;

    for (int i = tid; i < 50000 * KP; i += nthr) {
        int r = i / KP, col = i % KP;
        g_Ebf[i] = __float2bfloat16(col < 300 ? E[(size_t)r * 300 + col] : 0.0f);
    }
    for (int i = tid; i < 3 * NP * KP; i += nthr) {
        int mm = i / (NP * KP), r = (i / KP) % NP, col = i % KP;
        float v = (r < 1200 && col < 300) ? AWih[((size_t)mm * 1200 + r) * 300 + col] : 0.0f;
        g_Wbf[i] = __float2bfloat16(v);
    }
    // pack recurrent weights: g_WhhP[md][k][t][q] = W[md][gid = t + q*160][k], md 0..5 = A(m*2+dir), 6..7 = C(dir)
    for (int i = tid; i < 8 * 150 * 640; i += nthr) {
        int md = i / (150 * 640), r = i % (150 * 640);
        int k = r / 640, tq = r % 640;
        int t = tq >> 2, q = tq & 3;
        int gid = t + q * 160;
        float v = 0.0f;
        if (gid < 600) {
            if (md < 6) v = AWhh[((size_t)md * 600 + gid) * 150 + k];
            else        v = CWhh[((size_t)(md - 6) * 600 + gid) * 150 + k];
        }
        g_WhhP[i] = v;
    }
    for (int i = tid; i < 1200 * 303; i += nthr) {
        int c = i / 303, d = i % 303;
        g_CWihT[d * 1200 + c] = CWih[i];
    }
    for (int i = tid; i < 3 * 1200; i += nthr) g_bias2A[i] = Abih[i] + Abhh[i];
    for (int i = tid; i < 1200; i += nthr)     g_bias2C[i] = Cbih[i] + Cbhh[i];

    for (int i = tid; i < 640; i += nthr) {
        int c = 0;
        for (int t = 0; t < SL; t++) c += (tc[i * 53 + 3 + t] != 0);
        g_slens[i] = c;
    }
    for (int i = tid; i < 1600; i += nthr) {
        int c = 0;
        for (int t = 0; t < SL; t++) c += (uh[i * 50 + t] != 0);
        g_hlens[i] = c;
    }
    for (int i = tid; i < 32; i += nthr) {
        int c = 0;
        for (int t = 0; t < NT; t++) c += (tc[(i * NT + t) * 53 + 3] != 0);
        g_clens[i] = c;
    }
}

// ---------------- sort: descending-length order + valid-row maps ----------------
__global__ void sort_kernel()
{
    __shared__ int sl[1600];
    __shared__ int soff[1601];
    int g = blockIdx.x;
    int n = (g == 0) ? 640 : ((g == 1) ? 1600 : 32);
    const int* lens = (g == 0) ? g_slens : ((g == 1) ? g_hlens : g_clens);
    int* order = (g == 0) ? g_sorder : ((g == 1) ? g_horder : g_corder);
    int tid = threadIdx.x;

    for (int i = tid; i < n; i += 256) sl[i] = lens[i];
    __syncthreads();

    for (int i = tid; i < n; i += 256) {
        int li = sl[i], r = 0;
        for (int j = 0; j < n; j++) {
            int lj = sl[j];
            r += (lj > li) || (lj == li && j < i);
        }
        order[r] = i;
    }

    if (g < 2) {
        if (tid == 0) {
            int acc = 0;
            for (int i = 0; i < n; i++) { soff[i] = acc; acc += sl[i]; }
            g_vcount[g] = acc;
        }
        __syncthreads();
        int* rmap = (g == 0) ? g_rowmap0 : g_rowmapH;
        for (int i = tid; i < n; i += 256) {
            int off = soff[i], len = sl[i];
            for (int t = 0; t < len; t++) rmap[off + t] = i * 50 + t;
        }
    }
}

// ---------------- bf16 warp-MMA gx GEMM, A-resident, valid-row-compacted, fused ----------------
#define SSTRIDE 40               // bf16 elements per row in smem (80 B)
#define ACH 10240                // bytes per A K-chunk (128 rows * 80 B)
#define BST 10240                // bytes per B stage
#define SM_B_OFF (10 * ACH)
#define GSM_BYTES (10 * ACH + 4 * BST)   // 143360

__global__ void __launch_bounds__(256) gx_mma(const int* __restrict__ tc, const int* __restrict__ uh)
{
    __shared__ int sRow[128];
    extern __shared__ char smem[];
    uint32_t sA = smem_u32(smem);
    uint32_t sB = sA + SM_B_OFF;

    const int* tokb; int tstride, toff, nmats, which, blk;
    unsigned long long gxbase, gxstride;
    if (blockIdx.x < 250) {
        tokb = tc; tstride = 53; toff = 3; nmats = 1; which = 0; blk = blockIdx.x;
        gxbase = GX0_OFF; gxstride = 0ULL;
    } else {
        tokb = uh; tstride = 50; toff = 0; nmats = 3; which = 1; blk = blockIdx.x - 250;
        gxbase = GXH_OFF; gxstride = GXH_SZ;
    }

    int cnt = g_vcount[which];
    if (blk * 128 >= cnt) return;
    const int* rmap = which ? g_rowmapH : g_rowmap0;

    int tid  = threadIdx.x;
    int lane = tid & 31, wid = tid >> 5;
    int wm = wid & 3, wn = wid >> 2;

    if (tid < 128) {
        int gi = blk * 128 + tid;
        sRow[tid] = (gi < cnt) ? rmap[gi] : -1;
    }

    int lrow = tid >> 1, hf = tid & 1;
    int gi = blk * 128 + lrow;
    int tok = 0;
    if (gi < cnt) {
        int vrow = rmap[gi];
        int seq = vrow / 50, tt = vrow % 50;
        tok = tokb[seq * tstride + toff + tt];
    }
    const char* asrc = (const char*)(g_Ebf + (size_t)tok * KP);
#pragma unroll
    for (int ci = 0; ci < 5; ci++) {
        int c = ci * 2 + hf;
        uint32_t dst = sA + c * ACH + lrow * 80;
        const char* src = asrc + c * 64;
        CPA16(dst, src); CPA16(dst + 16, src + 16);
        CPA16(dst + 32, src + 32); CPA16(dst + 48, src + 48);
    }
    CPA_COMMIT();   // group: A

    int cofs = hf * 32;
    uint32_t dB0 = sB + lrow * 80 + cofs;
    int total = nmats * 100;

#pragma unroll
    for (int it = 0; it < 3; it++) {
        const char* src = (const char*)(g_Wbf + (size_t)lrow * KP + it * 32) + cofs;
        uint32_t dst = dB0 + it * BST;
        CPA16(dst, src); CPA16(dst + 16, src + 16);
        CPA_COMMIT();
    }

    int a_row  = wm * 32 + (lane & 15);
    int a_kofs = (lane >> 4) * 8;
    int b_row  = wn * 64 + ((lane >> 4) & 1) * 8 + (lane & 7);
    int b_kofs = ((lane >> 3) & 1) * 8;

    float acc[2][8][4];

#pragma unroll 1
    for (int it = 0; it < total; it++) {
        int k = it % 10;

        int rem = total - 1 - it;
        if (rem >= 2)      CPA_WAIT2();
        else if (rem == 1) CPA_WAIT1();
        else               CPA_WAIT0();
        __syncthreads();

        int itp = it + 3;
        if (itp < total) {
            int matp = itp / 100, ncp = (itp / 10) % 10, kp = itp % 10;
            const char* src = (const char*)(g_Wbf +
                ((size_t)matp * NP + ncp * 128 + lrow) * KP + kp * 32) + cofs;
            uint32_t dst = dB0 + (itp & 3) * BST;
            CPA16(dst, src); CPA16(dst + 16, src + 16);
            CPA_COMMIT();
        }

        if (k == 0) {
#pragma unroll
            for (int i = 0; i < 2; i++)
#pragma unroll
                for (int j = 0; j < 8; j++)
#pragma unroll
                    for (int q = 0; q < 4; q++) acc[i][j][q] = 0.0f;
        }

        uint32_t abase = sA + k * ACH;
        uint32_t bbase = sB + (it & 3) * BST;
#pragma unroll
        for (int ks = 0; ks < 2; ks++) {
            uint32_t afr[2][4];
#pragma unroll
            for (int mf = 0; mf < 2; mf++) {
                uint32_t addr = abase + (((a_row + mf * 16) * SSTRIDE) + ks * 16 + a_kofs) * 2;
                LDSM_X4(afr[mf][0], afr[mf][1], afr[mf][2], afr[mf][3], addr);
            }
            uint32_t bfr[4][4];
#pragma unroll
            for (int np = 0; np < 4; np++) {
                uint32_t addr = bbase + (((b_row + np * 16) * SSTRIDE) + ks * 16 + b_kofs) * 2;
                LDSM_X4(bfr[np][0], bfr[np][1], bfr[np][2], bfr[np][3], addr);
            }
#pragma unroll
            for (int mf = 0; mf < 2; mf++)
#pragma unroll
                for (int nf = 0; nf < 8; nf++) {
                    uint32_t b0 = bfr[nf >> 1][(nf & 1) * 2];
                    uint32_t b1 = bfr[nf >> 1][(nf & 1) * 2 + 1];
                    MMA16816(acc[mf][nf], afr[mf][0], afr[mf][1], afr[mf][2], afr[mf][3], b0, b1);
                }
        }

        if (k == 9) {
            int mat = it / 100, ncl = (it / 10) % 10;
            const float* bias = g_bias2A + mat * 1200;
            float* gxp = g_gx + gxbase + (size_t)mat * gxstride;
            int ocol0 = ncl * 128 + wn * 64 + (lane & 3) * 2;
#pragma unroll
            for (int mf = 0; mf < 2; mf++) {
                int r0i = wm * 32 + (lane >> 2) + mf * 16;
                int vr0 = sRow[r0i];
                int vr1 = sRow[r0i + 8];
                if (vr0 < 0 && vr1 < 0) continue;
#pragma unroll
                for (int nf = 0; nf < 8; nf++) {
                    int col = ocol0 + nf * 8;
                    if (col < 1200) {
                        float2 bv = *(const float2*)(bias + col);
                        if (vr0 >= 0)
                            *(float2*)(gxp + (size_t)vr0 * NCOL + col) =
                                make_float2(acc[mf][nf][0] + bv.x, acc[mf][nf][1] + bv.y);
                        if (vr1 >= 0)
                            *(float2*)(gxp + (size_t)vr1 * NCOL + col) =
                                make_float2(acc[mf][nf][2] + bv.x, acc[mf][nf][3] + bv.y);
                    }
                }
            }
        }
    }
}

// ---------------- conv-LSTM gx: feats[303] @ C_Wih^T + bias ----------------
__global__ void conv_gx_kernel(const int* __restrict__ tc)
{
    __shared__ float xs[8][304];
    int row0 = blockIdx.x * 8;
    int tid  = threadIdx.x;

    for (int i = tid; i < 8 * 300; i += 256) {
        int rr = i / 300, d = i % 300;
        xs[rr][d] = g_sentreps[(row0 + rr) * 300 + d];
    }
    if (tid < 24) {
        int rr = tid / 3, d = tid % 3;
        xs[rr][300 + d] = (float)tc[(row0 + rr) * 53 + d];
    }
    __syncthreads();

    for (int c = tid; c < NCOL; c += 256) {
        float a0 = g_bias2C[c], a1 = a0, a2 = a0, a3 = a0, a4 = a0, a5 = a0, a6 = a0, a7 = a0;
        for (int d = 0; d < 303; d++) {
            float w = g_CWihT[d * 1200 + c];
            a0 += xs[0][d] * w; a1 += xs[1][d] * w; a2 += xs[2][d] * w; a3 += xs[3][d] * w;
            a4 += xs[4][d] * w; a5 += xs[5][d] * w; a6 += xs[6][d] * w; a7 += xs[7][d] * w;
        }
        g_gxc[(size_t)(row0 + 0) * NCOL + c] = a0;
        g_gxc[(size_t)(row0 + 1) * NCOL + c] = a1;
        g_gxc[(size_t)(row0 + 2) * NCOL + c] = a2;
        g_gxc[(size_t)(row0 + 3) * NCOL + c] = a3;
        g_gxc[(size_t)(row0 + 4) * NCOL + c] = a4;
        g_gxc[(size_t)(row0 + 5) * NCOL + c] = a5;
        g_gxc[(size_t)(row0 + 6) * NCOL + c] = a6;
        g_gxc[(size_t)(row0 + 7) * NCOL + c] = a7;
    }
}

// ---------------- recurrent LSTM (persistent, sorted, early exit, f32x2 + packed W) ----------------
__global__ void __launch_bounds__(160) lstm_recur_all(int conv)
{
    const float* gx; const int* lens; float* finals;
    const int* order;
    int nSeq, T, blk, mb;
    if (conv) {
        mb = 3; gx = g_gxc; lens = g_clens; finals = g_u; order = g_corder;
        nSeq = 32; T = 20; blk = blockIdx.x;
    } else {
        int b = blockIdx.x;
        T = 50;
        if (b < 80) {
            blk = b; nSeq = 640; mb = 0; gx = g_gx;
            lens = g_slens; finals = g_sentreps; order = g_sorder;
        } else {
            int g = (b - 80) / 200;
            blk = (b - 80) % 200; nSeq = 1600; mb = g;
            gx = g_gx + GXH_OFF + (size_t)g * GXH_SZ;
            lens = g_hlens;
            finals = g_histreps + (size_t)g * 480000;
            order = g_horder;
        }
    }

    __shared__ float sh_h[150][16];    // transposed: [hidden-k][unit]
    __shared__ float sh_G[16][600];
    __shared__ int   sh_len[16], sh_seq[16];

    int tid = threadIdx.x;            // 160
    int u0  = blk * 16;
    int dir = (u0 >= nSeq) ? 1 : 0;   // nSeq is a multiple of 16

    if (tid < 16) {
        int idx = u0 + tid - dir * nSeq;
        int seq = order[idx];
        sh_seq[tid] = seq;
        sh_len[tid] = lens[seq];
    }
    for (int i = tid; i < 150 * 16; i += 160) ((float*)sh_h)[i] = 0.0f;
    __syncthreads();

    int Tmax = sh_len[0];             // descending order -> first is block max

    int mdi = (mb == 3) ? (6 + dir) : (mb * 2 + dir);
    const float4* wp = ((const float4*)g_WhhP) + (size_t)mdi * 150 * 160 + tid;

    int gA = tid, gB = tid + 160, gC = tid + 320, gD = tid + 480;
    bool vD = (gD < 600);

    uint32_t shh = smem_u32(sh_h);

    int uu = tid / 10;
    int j0 = (tid % 10) * 15;
    float c_reg[15];
#pragma unroll
    for (int m2 = 0; m2 < 15; m2++) c_reg[m2] = 0.0f;

    for (int s = 0; s < Tmax; s++) {
        unsigned long long acc2[4][8];
#pragma unroll
        for (int g = 0; g < 4; g++)
#pragma unroll
            for (int p = 0; p < 8; p++) acc2[g][p] = 0ULL;

        // distance-2 prefetched weight stream: one LDG.128 per k
        float4 Wc = wp[0];
        float4 Wn1 = wp[160];
#pragma unroll 2
        for (int k = 0; k < 150; k++) {
            float4 Wn2 = (k + 2 < 150) ? wp[(k + 2) * 160] : Wc;
            unsigned long long W0 = pack2(Wc.x);
            unsigned long long W1 = pack2(Wc.y);
            unsigned long long W2 = pack2(Wc.z);
            unsigned long long W3 = pack2(Wc.w);
            uint32_t hbase = shh + k * 64;
#pragma unroll
            for (int p = 0; p < 8; p++) {
                unsigned long long H = lds64(hbase + p * 8);
                fma2(acc2[0][p], W0, H);
                fma2(acc2[1][p], W1, H);
                fma2(acc2[2][p], W2, H);
                fma2(acc2[3][p], W3, H);
            }
            Wc = Wn1; Wn1 = Wn2;
        }

#pragma unroll 1
        for (int p = 0; p < 8; p++) {
            float a0l, a0h, a1l, a1h, a2l, a2h, a3l, a3h;
            unpack2(acc2[0][p], a0l, a0h);
            unpack2(acc2[1][p], a1l, a1h);
            unpack2(acc2[2][p], a2l, a2h);
            unpack2(acc2[3][p], a3l, a3h);
#pragma unroll
            for (int half = 0; half < 2; half++) {
                int u = 2 * p + half;
                int len = sh_len[u];
                if (s >= len) continue;
                int t = dir ? (len - 1 - s) : s;
                const float* gxr = gx + ((size_t)sh_seq[u] * T + t) * NCOL + dir * 600;
                sh_G[u][gA] = (half ? a0h : a0l) + gxr[gA];
                sh_G[u][gB] = (half ? a1h : a1l) + gxr[gB];
                sh_G[u][gC] = (half ? a2h : a2l) + gxr[gC];
                if (vD) sh_G[u][gD] = (half ? a3h : a3l) + gxr[gD];
            }
        }
        __syncthreads();

        {
            int len = sh_len[uu];
            if (s < len) {
#pragma unroll
                for (int m2 = 0; m2 < 15; m2++) {
                    int j = j0 + m2;
                    float gi = sh_G[uu][j];
                    float gf = sh_G[uu][150 + j];
                    float gg = sh_G[uu][300 + j];
                    float go = sh_G[uu][450 + j];
                    float cc = sigf(gf) * c_reg[m2] + sigf(gi) * tanhf(gg);
                    c_reg[m2] = cc;
                    sh_h[j][uu] = sigf(go) * tanhf(cc);
                }
            }
        }
        __syncthreads();
    }

    {
        int seq = sh_seq[uu];
#pragma unroll
        for (int m2 = 0; m2 < 15; m2++) {
            int j = j0 + m2;
            finals[(size_t)seq * 300 + dir * 150 + j] = sh_h[j][uu];
        }
    }
}

// ---------------- memory hops + output head ----------------
__global__ void hops_kernel(const float* __restrict__ Wout, const float* __restrict__ bout,
                            float* __restrict__ out)
{
    int b = blockIdx.x;
    int tid = threadIdx.x;   // 128
    __shared__ float su[300];
    __shared__ float sc[50];
    __shared__ float wr[4];

    for (int d = tid; d < 300; d += 128) su[d] = g_u[b * 300 + d];
    __syncthreads();

    for (int hop = 0; hop < 2; hop++) {
        const float* rep0 = g_histreps + (size_t)hop * 1600 * 300 + (size_t)b * 50 * 300;
        const float* rep1 = g_histreps + (size_t)(hop + 1) * 1600 * 300 + (size_t)b * 50 * 300;
        int w = tid >> 5, l = tid & 31;
        for (int n = w; n < 50; n += 4) {
            const float* r = rep0 + n * 300;
            float s = 0.0f;
            for (int d = l; d < 300; d += 32) s += r[d] * su[d];
#pragma unroll
            for (int o = 16; o; o >>= 1) s += __shfl_xor_sync(0xffffffffu, s, o);
            if (l == 0) sc[n] = s;
        }
        __syncthreads();
        if (tid < 32) {
            float mx = -1e30f;
            for (int n = tid; n < 50; n += 32) mx = fmaxf(mx, sc[n]);
#pragma unroll
            for (int o = 16; o; o >>= 1) mx = fmaxf(mx, __shfl_xor_sync(0xffffffffu, mx, o));
            float sum = 0.0f;
            for (int n = tid; n < 50; n += 32) { float v = __expf(sc[n] - mx); sc[n] = v; sum += v; }
#pragma unroll
            for (int o = 16; o; o >>= 1) sum += __shfl_xor_sync(0xffffffffu, sum, o);
            float inv = 1.0f / sum;
            for (int n = tid; n < 50; n += 32) sc[n] *= inv;
        }
        __syncthreads();
        for (int d = tid; d < 300; d += 128) {
            float acc = su[d];
            for (int n = 0; n < 50; n++) acc += sc[n] * rep1[n * 300 + d];
            su[d] = acc;
        }
        __syncthreads();
    }

    float s = 0.0f;
    for (int d = tid; d < 300; d += 128) s += su[d] * Wout[d];
#pragma unroll
    for (int o = 16; o; o >>= 1) s += __shfl_xor_sync(0xffffffffu, s, o);
    if ((tid & 31) == 0) wr[tid >> 5] = s;
    __syncthreads();
    if (tid == 0) {
        float t = wr[0] + wr[1] + wr[2] + wr[3];
        out[b] = 1.0f / (1.0f + __expf(-(t + bout[0])));
    }
}

// ---------------- launch ----------------
extern "C" void kernel_launch(void* const* d_in, const int* in_sizes, int n_in,
                              void* d_out, int out_size)
{
    const int*   tc   = (const int*)d_in[0];
    const int*   uh   = (const int*)d_in[1];
    const float* E    = (const float*)d_in[2];
    const float* AWih = (const float*)d_in[3];
    const float* AWhh = (const float*)d_in[4];
    const float* Abih = (const float*)d_in[5];
    const float* Abhh = (const float*)d_in[6];
    const float* CWih = (const float*)d_in[7];
    const float* CWhh = (const float*)d_in[8];
    const float* Cbih = (const float*)d_in[9];
    const float* Cbhh = (const float*)d_in[10];
    const float* Wout = (const float*)d_in[11];
    const float* bout = (const float*)d_in[12];
    float* out = (float*)d_out;

    cudaFuncSetAttribute(gx_mma, cudaFuncAttributeMaxDynamicSharedMemorySize, GSM_BYTES);

    setup_kernel<<<264, 256>>>(tc, uh, E, AWih, AWhh, Abih, Abhh, CWih, CWhh, Cbih, Cbhh);
    sort_kernel<<<3, 256>>>();

    // fused: blocks 0..249 target (A[0]), 250..874 history (all 3 matrices)
    gx_mma<<<875, 256, GSM_BYTES>>>(tc, uh);

    // all big recurrences in one launch (80 + 3*200 blocks)
    lstm_recur_all<<<680, 160>>>(0);

    // conversation-level biLSTM
    conv_gx_kernel<<<80, 256>>>(tc);
    lstm_recur_all<<<4, 160>>>(1);

    // memory hops + head
    hops_kernel<<<32, 128>>>(Wout, bout, out);
    (void)in_sizes; (void)n_in; (void)out_size;
}